// round 1
// baseline (speedup 1.0000x reference)
#include <cuda_runtime.h>
#include <cuda_bf16.h>
#include <cstdint>

// Problem constants
#define BATCH   4096
#define NTOK    49
#define DIM     256
#define NH      8
#define HD      32
#define MTOK    (BATCH * NTOK)      // 200704
#define QKV_N   (3 * DIM)           // 768
#define SCALE_F 0.17677669529663687f

// Scratch (device globals: allocation-free per harness rules)
__device__ float g_qkv[(size_t)MTOK * QKV_N];   // 616 MB
__device__ float g_attn[(size_t)MTOK * DIM];    // 205 MB

// ---------------------------------------------------------------------------
// TF32 GEMM: C[M,N] = A[M,K] * B[K,N] + bias[N]
// 128x128 block tile, BK=16, 8 warps (2x4), warp tile 64x32, mma m16n8k8.
// M,N assumed multiples of 128 (200704 = 128*1568; N in {768,256}).
// ---------------------------------------------------------------------------
#define BM 128
#define BN 128
#define BK 16
#define SA (BM + 4)   // As[k][m] stride
#define SB (BN + 4)   // Bs[k][n] stride (multiple of 4 for float4 stores)

__device__ __forceinline__ uint32_t f2tf32(float x) {
    uint32_t r;
    asm("cvt.rna.tf32.f32 %0, %1;" : "=r"(r) : "f"(x));
    return r;
}

__global__ __launch_bounds__(256, 2) void gemm_tf32_kernel(
    const float* __restrict__ A, const float* __restrict__ Bm,
    const float* __restrict__ bias, float* __restrict__ C,
    int M, int N, int K)
{
    __shared__ uint32_t As[BK][SA];
    __shared__ uint32_t Bs[BK][SB];

    const int tid  = threadIdx.x;
    const int lane = tid & 31;
    const int warp = tid >> 5;
    const int wm   = warp & 1;       // 2 warps along M
    const int wn   = warp >> 1;      // 4 warps along N
    const int bm   = blockIdx.y * BM;
    const int bn   = blockIdx.x * BN;
    const int tig  = lane & 3;       // thread-in-group
    const int grp  = lane >> 2;      // group id

    float c[4][4][4];
    #pragma unroll
    for (int mi = 0; mi < 4; mi++)
        #pragma unroll
        for (int ni = 0; ni < 4; ni++)
            #pragma unroll
            for (int r = 0; r < 4; r++) c[mi][ni][r] = 0.f;

    for (int k0 = 0; k0 < K; k0 += BK) {
        // Load A tile 128x16 (transposed into As[k][m])
        #pragma unroll
        for (int j = 0; j < 2; j++) {
            int l  = tid + j * 256;
            int ar = l >> 2;            // 0..127
            int kc = (l & 3) * 4;       // 0,4,8,12
            float4 v = *(const float4*)(A + (size_t)(bm + ar) * K + k0 + kc);
            As[kc + 0][ar] = f2tf32(v.x);
            As[kc + 1][ar] = f2tf32(v.y);
            As[kc + 2][ar] = f2tf32(v.z);
            As[kc + 3][ar] = f2tf32(v.w);
        }
        // Load B tile 16x128
        #pragma unroll
        for (int j = 0; j < 2; j++) {
            int l  = tid + j * 256;
            int br = l >> 5;            // 0..15
            int nc = (l & 31) * 4;
            float4 v = *(const float4*)(Bm + (size_t)(k0 + br) * N + bn + nc);
            Bs[br][nc + 0] = f2tf32(v.x);
            Bs[br][nc + 1] = f2tf32(v.y);
            Bs[br][nc + 2] = f2tf32(v.z);
            Bs[br][nc + 3] = f2tf32(v.w);
        }
        __syncthreads();

        #pragma unroll
        for (int kk = 0; kk < BK; kk += 8) {
            uint32_t a[4][4], b[4][2];
            #pragma unroll
            for (int mi = 0; mi < 4; mi++) {
                int row = wm * 64 + mi * 16 + grp;
                a[mi][0] = As[kk + tig][row];
                a[mi][1] = As[kk + tig][row + 8];
                a[mi][2] = As[kk + tig + 4][row];
                a[mi][3] = As[kk + tig + 4][row + 8];
            }
            #pragma unroll
            for (int ni = 0; ni < 4; ni++) {
                int col = wn * 32 + ni * 8 + grp;
                b[ni][0] = Bs[kk + tig][col];
                b[ni][1] = Bs[kk + tig + 4][col];
            }
            #pragma unroll
            for (int mi = 0; mi < 4; mi++)
                #pragma unroll
                for (int ni = 0; ni < 4; ni++)
                    asm volatile(
                        "mma.sync.aligned.m16n8k8.row.col.f32.tf32.tf32.f32 "
                        "{%0,%1,%2,%3},{%4,%5,%6,%7},{%8,%9},{%0,%1,%2,%3};"
                        : "+f"(c[mi][ni][0]), "+f"(c[mi][ni][1]),
                          "+f"(c[mi][ni][2]), "+f"(c[mi][ni][3])
                        : "r"(a[mi][0]), "r"(a[mi][1]), "r"(a[mi][2]), "r"(a[mi][3]),
                          "r"(b[ni][0]), "r"(b[ni][1]));
        }
        __syncthreads();
    }

    // Epilogue: C = acc + bias
    #pragma unroll
    for (int mi = 0; mi < 4; mi++) {
        int row0 = bm + wm * 64 + mi * 16 + grp;
        #pragma unroll
        for (int ni = 0; ni < 4; ni++) {
            int col0 = bn + wn * 32 + ni * 8 + tig * 2;
            float bi0 = bias[col0], bi1 = bias[col0 + 1];
            C[(size_t)row0 * N + col0]           = c[mi][ni][0] + bi0;
            C[(size_t)row0 * N + col0 + 1]       = c[mi][ni][1] + bi1;
            C[(size_t)(row0 + 8) * N + col0]     = c[mi][ni][2] + bi0;
            C[(size_t)(row0 + 8) * N + col0 + 1] = c[mi][ni][3] + bi1;
        }
    }
}

// ---------------------------------------------------------------------------
// Fused window attention: one block per (window b, head h).
// scores = (q*scale)·k^T + rpb[relidx] + mask; softmax; out = p·v
// qkv layout per token: [3][NH][HD] contiguous (768 floats).
// ---------------------------------------------------------------------------
__global__ __launch_bounds__(128) void attn_kernel(
    const float* __restrict__ qkv, const float* __restrict__ mask,
    const float* __restrict__ rpb, float* __restrict__ out)
{
    const int bh = blockIdx.x;
    const int h  = bh & (NH - 1);
    const int b  = bh >> 3;
    const int tid = threadIdx.x;

    __shared__ float q[NTOK][HD + 1];
    __shared__ float k[NTOK][HD + 1];
    __shared__ float v[NTOK][HD + 1];
    __shared__ float s[NTOK][NTOK + 1];

    const float* base = qkv + (size_t)b * NTOK * QKV_N + h * HD;
    for (int idx = tid; idx < NTOK * HD; idx += 128) {
        int n = idx >> 5, d = idx & 31;
        const float* t = base + (size_t)n * QKV_N + d;
        q[n][d] = t[0] * SCALE_F;
        k[n][d] = t[DIM];
        v[n][d] = t[2 * DIM];
    }
    __syncthreads();

    const float* mptr = mask + (size_t)b * NTOK * NTOK;
    for (int idx = tid; idx < NTOK * NTOK; idx += 128) {
        int i = idx / NTOK, j = idx - i * NTOK;
        float acc = 0.f;
        #pragma unroll
        for (int d = 0; d < HD; d++) acc += q[i][d] * k[j][d];
        int ri = i / 7, ci = i - ri * 7;
        int rj = j / 7, cj = j - rj * 7;
        int ridx = (ri - rj + 6) * 13 + (ci - cj + 6);
        s[i][j] = acc + rpb[ridx * NH + h] + mptr[idx];
    }
    __syncthreads();

    // Softmax: one thread per row
    if (tid < NTOK) {
        float m = -1e30f;
        #pragma unroll
        for (int j = 0; j < NTOK; j++) m = fmaxf(m, s[tid][j]);
        float sum = 0.f;
        #pragma unroll
        for (int j = 0; j < NTOK; j++) {
            float e = __expf(s[tid][j] - m);
            s[tid][j] = e;
            sum += e;
        }
        float inv = 1.f / sum;
        #pragma unroll
        for (int j = 0; j < NTOK; j++) s[tid][j] *= inv;
    }
    __syncthreads();

    float* optr = out + (size_t)b * NTOK * DIM + h * HD;
    for (int idx = tid; idx < NTOK * HD; idx += 128) {
        int i = idx >> 5, d = idx & 31;
        float acc = 0.f;
        #pragma unroll
        for (int j = 0; j < NTOK; j++) acc += s[i][j] * v[j][d];
        optr[(size_t)i * DIM + d] = acc;
    }
}

// ---------------------------------------------------------------------------
extern "C" void kernel_launch(void* const* d_in, const int* in_sizes, int n_in,
                              void* d_out, int out_size)
{
    const float* x      = (const float*)d_in[0];
    const float* mask   = (const float*)d_in[1];
    const float* qkv_w  = (const float*)d_in[2];
    const float* qkv_b  = (const float*)d_in[3];
    const float* rpb    = (const float*)d_in[4];
    const float* proj_w = (const float*)d_in[5];
    const float* proj_b = (const float*)d_in[6];
    float* out = (float*)d_out;

    float *qkv_buf = nullptr, *attn_buf = nullptr;
    cudaGetSymbolAddress((void**)&qkv_buf, g_qkv);
    cudaGetSymbolAddress((void**)&attn_buf, g_attn);

    // 1) QKV GEMM: [200704,256] x [256,768]
    gemm_tf32_kernel<<<dim3(QKV_N / BN, MTOK / BM), 256>>>(
        x, qkv_w, qkv_b, qkv_buf, MTOK, QKV_N, DIM);

    // 2) Fused window attention per (b,h)
    attn_kernel<<<BATCH * NH, 128>>>(qkv_buf, mask, rpb, attn_buf);

    // 3) Proj GEMM: [200704,256] x [256,256]
    gemm_tf32_kernel<<<dim3(DIM / BN, MTOK / BM), 256>>>(
        attn_buf, proj_w, proj_b, out, MTOK, DIM, DIM);
}

// round 2
// speedup vs baseline: 1.4176x; 1.4176x over previous
#include <cuda_runtime.h>
#include <cuda_bf16.h>
#include <cstdint>

// Problem constants
#define BATCH   4096
#define NTOK    49
#define DIM     256
#define NH      8
#define HD      32
#define MTOK    (BATCH * NTOK)      // 200704
#define QKV_N   (3 * DIM)           // 768
#define KDIM    256
#define SCALE_F 0.17677669529663687f

// Scratch (device globals: allocation-free per harness rules)
__device__ float g_qkv[(size_t)MTOK * QKV_N];   // 616 MB
__device__ float g_attn[(size_t)MTOK * DIM];    // 205 MB
__device__ float g_wT1[QKV_N * DIM];            // qkv_w transposed [768][256]
__device__ float g_wT2[DIM * DIM];              // proj_w transposed [256][256]

__device__ __forceinline__ uint32_t f2tf32(float x) {
    uint32_t r;
    asm("cvt.rna.tf32.f32 %0, %1;" : "=r"(r) : "f"(x));
    return r;
}

__device__ __forceinline__ void cp_async16(void* smem_dst, const void* gptr) {
    uint32_t s = (uint32_t)__cvta_generic_to_shared(smem_dst);
    asm volatile("cp.async.cg.shared.global [%0], [%1], 16;\n" :: "r"(s), "l"(gptr));
}
#define CP_COMMIT()  asm volatile("cp.async.commit_group;\n" ::: "memory")
#define CP_WAIT(n)   asm volatile("cp.async.wait_group %0;\n" :: "n"(n) : "memory")

// ---------------------------------------------------------------------------
// Weight transpose: in[R][C] -> out[C][R]  (tiny matrices, runs every launch)
// ---------------------------------------------------------------------------
__global__ void transpose_kernel(const float* __restrict__ in, float* __restrict__ out,
                                 int R, int C) {
    int idx = blockIdx.x * 256 + threadIdx.x;
    if (idx < R * C) {
        int r = idx / C, c = idx - r * C;
        out[c * R + r] = in[idx];
    }
}

// ---------------------------------------------------------------------------
// TF32 GEMM v2: C[M,N] = A[M,256] * BT[N,256]^T + bias[N]
// 128x128 block, BK=16, 4-stage cp.async pipeline, 8 warps (2x4), warp 64x32.
// Both A and BT tiles stored as [row][16] in smem; all fragment loads are
// conflict-free LDS.128 via k-permutation (lane tig holds physical k 4t..4t+3).
// ---------------------------------------------------------------------------
#define BM 128
#define BN 128
#define BK 16
#define STAGES 4
#define STG_F (BM * BK)             // 2048 floats per tile per stage
#define GEMM_SMEM (STAGES * 2 * STG_F * 4)  // 65536 bytes

__global__ __launch_bounds__(256, 2) void gemm_tf32_v2(
    const float* __restrict__ A, const float* __restrict__ BT,
    const float* __restrict__ bias, float* __restrict__ C, int N)
{
    extern __shared__ float sm[];
    float* AsBase = sm;
    float* BsBase = sm + STAGES * STG_F;

    const int tid  = threadIdx.x;
    const int lane = tid & 31;
    const int warp = tid >> 5;
    const int wm   = warp & 1;
    const int wn   = warp >> 1;
    const int bm   = blockIdx.y * BM;
    const int bn   = blockIdx.x * BN;
    const int tig  = lane & 3;
    const int grp  = lane >> 2;

    const int r_ld  = tid >> 2;          // 0..63  (+64 on second chunk)
    const int c4_ld = (tid & 3) * 4;

    float c[4][4][4];
    #pragma unroll
    for (int mi = 0; mi < 4; mi++)
        #pragma unroll
        for (int ni = 0; ni < 4; ni++)
            #pragma unroll
            for (int r = 0; r < 4; r++) c[mi][ni][r] = 0.f;

    auto load_stage = [&](int slot, int kt) {
        float* as = AsBase + slot * STG_F;
        float* bs = BsBase + slot * STG_F;
        const float* ag = A  + (size_t)bm * KDIM + kt * BK;
        const float* bg = BT + (size_t)bn * KDIM + kt * BK;
        #pragma unroll
        for (int j = 0; j < 2; j++) {
            int r = r_ld + j * 64;
            cp_async16(as + r * BK + c4_ld, ag + (size_t)r * KDIM + c4_ld);
            cp_async16(bs + r * BK + c4_ld, bg + (size_t)r * KDIM + c4_ld);
        }
    };

    const int ITERS = KDIM / BK;   // 16
    #pragma unroll
    for (int p = 0; p < STAGES - 1; p++) { load_stage(p, p); CP_COMMIT(); }

    for (int it = 0; it < ITERS; it++) {
        CP_WAIT(STAGES - 2);
        __syncthreads();

        int nk = it + STAGES - 1;
        if (nk < ITERS) load_stage(nk & (STAGES - 1), nk);
        CP_COMMIT();

        const float* as = AsBase + (it & (STAGES - 1)) * STG_F;
        const float* bs = BsBase + (it & (STAGES - 1)) * STG_F;

        // A fragments: 8 conflict-free LDS.128 (covers all of BK=16)
        uint32_t Af[4][2][4];
        #pragma unroll
        for (int mi = 0; mi < 4; mi++) {
            int row = wm * 64 + mi * 16 + grp;
            #pragma unroll
            for (int r = 0; r < 2; r++) {
                float4 t = *(const float4*)(as + (row + r * 8) * BK + 4 * tig);
                Af[mi][r][0] = f2tf32(t.x); Af[mi][r][1] = f2tf32(t.y);
                Af[mi][r][2] = f2tf32(t.z); Af[mi][r][3] = f2tf32(t.w);
            }
        }
        #pragma unroll
        for (int ni = 0; ni < 4; ni++) {
            int col = wn * 32 + ni * 8 + grp;
            float4 t = *(const float4*)(bs + col * BK + 4 * tig);
            uint32_t b0 = f2tf32(t.x), b1 = f2tf32(t.y);
            uint32_t b2 = f2tf32(t.z), b3 = f2tf32(t.w);
            #pragma unroll
            for (int mi = 0; mi < 4; mi++) {
                asm volatile(
                    "mma.sync.aligned.m16n8k8.row.col.f32.tf32.tf32.f32 "
                    "{%0,%1,%2,%3},{%4,%5,%6,%7},{%8,%9},{%0,%1,%2,%3};"
                    : "+f"(c[mi][ni][0]), "+f"(c[mi][ni][1]),
                      "+f"(c[mi][ni][2]), "+f"(c[mi][ni][3])
                    : "r"(Af[mi][0][0]), "r"(Af[mi][1][0]),
                      "r"(Af[mi][0][1]), "r"(Af[mi][1][1]),
                      "r"(b0), "r"(b1));
                asm volatile(
                    "mma.sync.aligned.m16n8k8.row.col.f32.tf32.tf32.f32 "
                    "{%0,%1,%2,%3},{%4,%5,%6,%7},{%8,%9},{%0,%1,%2,%3};"
                    : "+f"(c[mi][ni][0]), "+f"(c[mi][ni][1]),
                      "+f"(c[mi][ni][2]), "+f"(c[mi][ni][3])
                    : "r"(Af[mi][0][2]), "r"(Af[mi][1][2]),
                      "r"(Af[mi][0][3]), "r"(Af[mi][1][3]),
                      "r"(b2), "r"(b3));
            }
        }
    }

    // Epilogue: C = acc + bias
    #pragma unroll
    for (int mi = 0; mi < 4; mi++) {
        int row0 = bm + wm * 64 + mi * 16 + grp;
        #pragma unroll
        for (int ni = 0; ni < 4; ni++) {
            int col0 = bn + wn * 32 + ni * 8 + tig * 2;
            float bi0 = bias[col0], bi1 = bias[col0 + 1];
            C[(size_t)row0 * N + col0]           = c[mi][ni][0] + bi0;
            C[(size_t)row0 * N + col0 + 1]       = c[mi][ni][1] + bi1;
            C[(size_t)(row0 + 8) * N + col0]     = c[mi][ni][2] + bi0;
            C[(size_t)(row0 + 8) * N + col0 + 1] = c[mi][ni][3] + bi1;
        }
    }
}

// ---------------------------------------------------------------------------
// Fused window attention v2: one block per (window b, head h), 128 threads.
// Register-tiled 4x4; transposed smem layouts make all hot loads LDS.128.
// ---------------------------------------------------------------------------
#define NP 52   // padded token count (mult of 4)

__global__ __launch_bounds__(128) void attn_v2(
    const float* __restrict__ qkv, const float* __restrict__ mask,
    const float* __restrict__ rpb, float* __restrict__ out)
{
    __shared__ float qT[HD][NP];      // [d][i], q * scale
    __shared__ float kT[HD][NP];      // [d][j]
    __shared__ float vS[NTOK][36];    // [j][d]
    __shared__ float sT[NP][NP];      // [j][i]

    const int bh  = blockIdx.x;
    const int h   = bh & (NH - 1);
    const int b   = bh >> 3;
    const int tid = threadIdx.x;

    const float* base = qkv + (size_t)b * NTOK * QKV_N + h * HD;
    for (int idx = tid; idx < NTOK * 8; idx += 128) {
        int n = idx >> 3, d4 = (idx & 7) * 4;
        const float* t = base + (size_t)n * QKV_N + d4;
        float4 qv = *(const float4*)(t);
        float4 kv = *(const float4*)(t + DIM);
        float4 vv = *(const float4*)(t + 2 * DIM);
        qT[d4 + 0][n] = qv.x * SCALE_F; qT[d4 + 1][n] = qv.y * SCALE_F;
        qT[d4 + 2][n] = qv.z * SCALE_F; qT[d4 + 3][n] = qv.w * SCALE_F;
        kT[d4 + 0][n] = kv.x; kT[d4 + 1][n] = kv.y;
        kT[d4 + 2][n] = kv.z; kT[d4 + 3][n] = kv.w;
        *(float4*)&vS[n][d4] = vv;
    }
    __syncthreads();

    // ---- Scores: S = (q s)·k^T + rpb + mask, tiled 4x4 over 13x13 tiles
    const float* mrow = mask + (size_t)b * NTOK * NTOK;
    for (int t = tid; t < 169; t += 128) {
        int ti = t % 13, tj = t / 13;
        int i0 = ti * 4, j0 = tj * 4;
        float acc[4][4] = {};
        #pragma unroll
        for (int d = 0; d < HD; d++) {
            float4 qa4 = *(const float4*)&qT[d][i0];
            float4 kb4 = *(const float4*)&kT[d][j0];
            float qa[4] = {qa4.x, qa4.y, qa4.z, qa4.w};
            float kb[4] = {kb4.x, kb4.y, kb4.z, kb4.w};
            #pragma unroll
            for (int mi = 0; mi < 4; mi++)
                #pragma unroll
                for (int nj = 0; nj < 4; nj++)
                    acc[mi][nj] += qa[mi] * kb[nj];
        }
        #pragma unroll
        for (int nj = 0; nj < 4; nj++) {
            int j = j0 + nj;
            if (j >= NTOK) break;
            int rj = j / 7, cj = j - rj * 7;
            #pragma unroll
            for (int mi = 0; mi < 4; mi++) {
                int i = i0 + mi;
                if (i < NTOK) {
                    int ri = i / 7, ci = i - ri * 7;
                    int ridx = (ri - rj + 6) * 13 + (ci - cj + 6);
                    sT[j][i] = acc[mi][nj] + rpb[ridx * NH + h] + mrow[i * NTOK + j];
                }
            }
        }
    }
    __syncthreads();

    // ---- Softmax over j for each row i (column of sT)
    if (tid < NTOK) {
        int i = tid;
        float mx = -1e30f;
        #pragma unroll
        for (int j = 0; j < NTOK; j++) mx = fmaxf(mx, sT[j][i]);
        float sum = 0.f;
        #pragma unroll
        for (int j = 0; j < NTOK; j++) {
            float e = __expf(sT[j][i] - mx);
            sT[j][i] = e;
            sum += e;
        }
        float inv = 1.f / sum;
        #pragma unroll
        for (int j = 0; j < NTOK; j++) sT[j][i] *= inv;
    }
    __syncthreads();

    // ---- PV: out[i][d] = sum_j p[i][j] v[j][d], tiled 4i x 4d (13x8 tiles)
    if (tid < 104) {
        int ti = tid % 13, td = tid / 13;
        int i0 = ti * 4, d0 = td * 4;
        float acc[4][4] = {};
        for (int j = 0; j < NTOK; j++) {
            float4 p4 = *(const float4*)&sT[j][i0];
            float4 v4 = *(const float4*)&vS[j][d0];
            float p[4] = {p4.x, p4.y, p4.z, p4.w};
            float v[4] = {v4.x, v4.y, v4.z, v4.w};
            #pragma unroll
            for (int mi = 0; mi < 4; mi++)
                #pragma unroll
                for (int nd = 0; nd < 4; nd++)
                    acc[mi][nd] += p[mi] * v[nd];
        }
        #pragma unroll
        for (int mi = 0; mi < 4; mi++) {
            int i = i0 + mi;
            if (i < NTOK) {
                float4 o = make_float4(acc[mi][0], acc[mi][1], acc[mi][2], acc[mi][3]);
                *(float4*)&out[((size_t)b * NTOK + i) * DIM + h * HD + d0] = o;
            }
        }
    }
}

// ---------------------------------------------------------------------------
extern "C" void kernel_launch(void* const* d_in, const int* in_sizes, int n_in,
                              void* d_out, int out_size)
{
    const float* x      = (const float*)d_in[0];
    const float* mask   = (const float*)d_in[1];
    const float* qkv_w  = (const float*)d_in[2];
    const float* qkv_b  = (const float*)d_in[3];
    const float* rpb    = (const float*)d_in[4];
    const float* proj_w = (const float*)d_in[5];
    const float* proj_b = (const float*)d_in[6];
    float* out = (float*)d_out;

    float *qkv_buf, *attn_buf, *wT1, *wT2;
    cudaGetSymbolAddress((void**)&qkv_buf, g_qkv);
    cudaGetSymbolAddress((void**)&attn_buf, g_attn);
    cudaGetSymbolAddress((void**)&wT1, g_wT1);
    cudaGetSymbolAddress((void**)&wT2, g_wT2);

    cudaFuncSetAttribute(gemm_tf32_v2,
                         cudaFuncAttributeMaxDynamicSharedMemorySize, GEMM_SMEM);

    // 0) Transpose weights (tiny)
    transpose_kernel<<<(DIM * QKV_N + 255) / 256, 256>>>(qkv_w, wT1, DIM, QKV_N);
    transpose_kernel<<<(DIM * DIM + 255) / 256, 256>>>(proj_w, wT2, DIM, DIM);

    // 1) QKV GEMM: [200704,256] x [256,768]
    gemm_tf32_v2<<<dim3(QKV_N / BN, MTOK / BM), 256, GEMM_SMEM>>>(
        x, wT1, qkv_b, qkv_buf, QKV_N);

    // 2) Fused window attention per (b,h)
    attn_v2<<<BATCH * NH, 128>>>(qkv_buf, mask, rpb, attn_buf);

    // 3) Proj GEMM: [200704,256] x [256,256]
    gemm_tf32_v2<<<dim3(DIM / BN, MTOK / BM), 256, GEMM_SMEM>>>(
        attn_buf, wT2, proj_b, out, DIM);
}

// round 3
// speedup vs baseline: 1.8778x; 1.3247x over previous
#include <cuda_runtime.h>
#include <cuda_bf16.h>
#include <cstdint>

// Problem constants
#define BATCH   4096
#define NTOK    49
#define DIM     256
#define NH      8
#define HD      32
#define MTOK    (BATCH * NTOK)      // 200704
#define QKV_N   (3 * DIM)           // 768
#define KDIM    256
#define SCALE_F 0.17677669529663687f

// Scratch (device globals)
__device__ float g_qkv[(size_t)MTOK * QKV_N];
__device__ float g_attn[(size_t)MTOK * DIM];
__device__ float g_wT1[QKV_N * DIM];
__device__ float g_wT2[DIM * DIM];
__device__ float g_bias[NH * NTOK * NTOK];      // expanded rpb [h][i][j]

__device__ __forceinline__ uint32_t f2tf32(float x) {
    uint32_t r;
    asm("cvt.rna.tf32.f32 %0, %1;" : "=r"(r) : "f"(x));
    return r;
}
__device__ __forceinline__ float tf32f(float x) { return __uint_as_float(f2tf32(x)); }

__device__ __forceinline__ void mma_tf32(float c[4], uint32_t a0, uint32_t a1,
                                         uint32_t a2, uint32_t a3,
                                         uint32_t b0, uint32_t b1) {
    asm volatile(
        "mma.sync.aligned.m16n8k8.row.col.f32.tf32.tf32.f32 "
        "{%0,%1,%2,%3},{%4,%5,%6,%7},{%8,%9},{%0,%1,%2,%3};"
        : "+f"(c[0]), "+f"(c[1]), "+f"(c[2]), "+f"(c[3])
        : "r"(a0), "r"(a1), "r"(a2), "r"(a3), "r"(b0), "r"(b1));
}

__device__ __forceinline__ void cp_async16(void* smem_dst, const void* gptr) {
    uint32_t s = (uint32_t)__cvta_generic_to_shared(smem_dst);
    asm volatile("cp.async.cg.shared.global [%0], [%1], 16;\n" :: "r"(s), "l"(gptr));
}
#define CP_COMMIT()  asm volatile("cp.async.commit_group;\n" ::: "memory")
#define CP_WAIT(n)   asm volatile("cp.async.wait_group %0;\n" :: "n"(n) : "memory")

// ---------------------------------------------------------------------------
// Weight transpose + tf32 pre-round: in[R][C] -> out[C][R]
// ---------------------------------------------------------------------------
__global__ void transpose_kernel(const float* __restrict__ in, float* __restrict__ out,
                                 int R, int C) {
    int idx = blockIdx.x * 256 + threadIdx.x;
    if (idx < R * C) {
        int r = idx / C, c = idx - r * C;
        out[c * R + r] = tf32f(in[idx]);
    }
}

// Expand rpb table to dense bias[h][i][j]
__global__ void bias_expand_kernel(const float* __restrict__ rpb, float* __restrict__ bias) {
    int idx = blockIdx.x * 256 + threadIdx.x;
    if (idx < NH * NTOK * NTOK) {
        int h = idx / (NTOK * NTOK), r = idx % (NTOK * NTOK);
        int i = r / NTOK, j = r % NTOK;
        int ri = i / 7, ci = i - ri * 7;
        int rj = j / 7, cj = j - rj * 7;
        int ridx = (ri - rj + 6) * 13 + (ci - cj + 6);
        bias[idx] = rpb[ridx * NH + h];
    }
}

// ---------------------------------------------------------------------------
// TF32 GEMM: C[M,N] = A[M,256] * BT[N,256]^T + bias[N]
// BT pre-rounded to tf32. CVT_A: round A on fragment load. ROUND_OUT: store tf32.
// ---------------------------------------------------------------------------
#define BM 128
#define BN 128
#define BK 16
#define STAGES 4
#define STG_F (BM * BK)
#define GEMM_SMEM (STAGES * 2 * STG_F * 4)

template<bool CVT_A, bool ROUND_OUT>
__global__ __launch_bounds__(256, 2) void gemm_tf32_v3(
    const float* __restrict__ A, const float* __restrict__ BT,
    const float* __restrict__ bias, float* __restrict__ C, int N)
{
    extern __shared__ float sm[];
    float* AsBase = sm;
    float* BsBase = sm + STAGES * STG_F;

    const int tid  = threadIdx.x;
    const int lane = tid & 31;
    const int warp = tid >> 5;
    const int wm   = warp & 1;
    const int wn   = warp >> 1;
    const int bm   = blockIdx.y * BM;
    const int bn   = blockIdx.x * BN;
    const int tig  = lane & 3;
    const int grp  = lane >> 2;

    const int r_ld  = tid >> 2;
    const int c4_ld = (tid & 3) * 4;

    float c[4][4][4];
    #pragma unroll
    for (int mi = 0; mi < 4; mi++)
        #pragma unroll
        for (int ni = 0; ni < 4; ni++)
            #pragma unroll
            for (int r = 0; r < 4; r++) c[mi][ni][r] = 0.f;

    auto load_stage = [&](int slot, int kt) {
        float* as = AsBase + slot * STG_F;
        float* bs = BsBase + slot * STG_F;
        const float* ag = A  + (size_t)bm * KDIM + kt * BK;
        const float* bg = BT + (size_t)bn * KDIM + kt * BK;
        #pragma unroll
        for (int j = 0; j < 2; j++) {
            int r = r_ld + j * 64;
            cp_async16(as + r * BK + c4_ld, ag + (size_t)r * KDIM + c4_ld);
            cp_async16(bs + r * BK + c4_ld, bg + (size_t)r * KDIM + c4_ld);
        }
    };

    const int ITERS = KDIM / BK;
    #pragma unroll
    for (int p = 0; p < STAGES - 1; p++) { load_stage(p, p); CP_COMMIT(); }

    for (int it = 0; it < ITERS; it++) {
        CP_WAIT(STAGES - 2);
        __syncthreads();

        int nk = it + STAGES - 1;
        if (nk < ITERS) load_stage(nk & (STAGES - 1), nk);
        CP_COMMIT();

        const float* as = AsBase + (it & (STAGES - 1)) * STG_F;
        const float* bs = BsBase + (it & (STAGES - 1)) * STG_F;

        uint32_t Af[4][2][4];
        #pragma unroll
        for (int mi = 0; mi < 4; mi++) {
            int row = wm * 64 + mi * 16 + grp;
            #pragma unroll
            for (int r = 0; r < 2; r++) {
                float4 t = *(const float4*)(as + (row + r * 8) * BK + 4 * tig);
                if (CVT_A) {
                    Af[mi][r][0] = f2tf32(t.x); Af[mi][r][1] = f2tf32(t.y);
                    Af[mi][r][2] = f2tf32(t.z); Af[mi][r][3] = f2tf32(t.w);
                } else {
                    Af[mi][r][0] = __float_as_uint(t.x); Af[mi][r][1] = __float_as_uint(t.y);
                    Af[mi][r][2] = __float_as_uint(t.z); Af[mi][r][3] = __float_as_uint(t.w);
                }
            }
        }
        #pragma unroll
        for (int ni = 0; ni < 4; ni++) {
            int col = wn * 32 + ni * 8 + grp;
            float4 t = *(const float4*)(bs + col * BK + 4 * tig);
            uint32_t b0 = __float_as_uint(t.x), b1 = __float_as_uint(t.y);
            uint32_t b2 = __float_as_uint(t.z), b3 = __float_as_uint(t.w);
            #pragma unroll
            for (int mi = 0; mi < 4; mi++) {
                mma_tf32(c[mi][ni], Af[mi][0][0], Af[mi][1][0],
                         Af[mi][0][1], Af[mi][1][1], b0, b1);
                mma_tf32(c[mi][ni], Af[mi][0][2], Af[mi][1][2],
                         Af[mi][0][3], Af[mi][1][3], b2, b3);
            }
        }
    }

    #pragma unroll
    for (int mi = 0; mi < 4; mi++) {
        int row0 = bm + wm * 64 + mi * 16 + grp;
        #pragma unroll
        for (int ni = 0; ni < 4; ni++) {
            int col0 = bn + wn * 32 + ni * 8 + tig * 2;
            float bi0 = bias[col0], bi1 = bias[col0 + 1];
            float v00 = c[mi][ni][0] + bi0, v01 = c[mi][ni][1] + bi1;
            float v10 = c[mi][ni][2] + bi0, v11 = c[mi][ni][3] + bi1;
            if (ROUND_OUT) { v00 = tf32f(v00); v01 = tf32f(v01); v10 = tf32f(v10); v11 = tf32f(v11); }
            C[(size_t)row0 * N + col0]           = v00;
            C[(size_t)row0 * N + col0 + 1]       = v01;
            C[(size_t)(row0 + 8) * N + col0]     = v10;
            C[(size_t)(row0 + 8) * N + col0 + 1] = v11;
        }
    }
}

// ---------------------------------------------------------------------------
// Fused window attention v3: one block per (b,h), 4 warps, warp-level tf32 MMA.
// i padded to 64 (4 warps x m16), j padded to 56 (7 n-tiles x 8).
// All smem operands stored pre-rounded to tf32.
// ---------------------------------------------------------------------------
#define SQ 36   // Q/K row stride (perfect 4-phase float4 frag loads)
#define SJ 68   // P/VT row stride (perfect 2-phase float2 frag loads)

__global__ __launch_bounds__(128) void attn_v3(
    const float* __restrict__ qkv, const float* __restrict__ mask,
    const float* __restrict__ bias, float* __restrict__ out)
{
    __shared__ float Qs[64][SQ];      // [i][d] tf32(q*scale)
    __shared__ float Ks[56][SQ];      // [j][d] tf32(k)
    __shared__ float vT[32][SJ];      // [d][j] tf32(v)
    __shared__ float sT[64][SJ];      // [i][j] tf32(p)

    const int bh   = blockIdx.x;
    const int h    = bh & (NH - 1);
    const int b    = bh >> 3;
    const int tid  = threadIdx.x;
    const int lane = tid & 31;
    const int warp = tid >> 5;
    const int tig  = lane & 3;
    const int grp  = lane >> 2;
    const int wrow = warp * 16;

    // Zero pad regions (avoid NaN/Inf from uninit smem)
    for (int idx = tid; idx < 15 * SQ; idx += 128) Qs[49 + idx / SQ][idx % SQ] = 0.f;
    for (int idx = tid; idx < 7 * SQ;  idx += 128) Ks[49 + idx / SQ][idx % SQ] = 0.f;
    for (int idx = tid; idx < 32 * 20; idx += 128) vT[idx / 20][48 + idx % 20] = 0.f;

    const float* basep = qkv + (size_t)b * NTOK * QKV_N + h * HD;
    for (int idx = tid; idx < NTOK * 8; idx += 128) {
        int n = idx >> 3, d4 = (idx & 7) * 4;
        const float* t = basep + (size_t)n * QKV_N + d4;
        float4 qv = *(const float4*)(t);
        float4 kv = *(const float4*)(t + DIM);
        float4 vv = *(const float4*)(t + 2 * DIM);
        Qs[n][d4 + 0] = tf32f(qv.x * SCALE_F); Qs[n][d4 + 1] = tf32f(qv.y * SCALE_F);
        Qs[n][d4 + 2] = tf32f(qv.z * SCALE_F); Qs[n][d4 + 3] = tf32f(qv.w * SCALE_F);
        Ks[n][d4 + 0] = tf32f(kv.x); Ks[n][d4 + 1] = tf32f(kv.y);
        Ks[n][d4 + 2] = tf32f(kv.z); Ks[n][d4 + 3] = tf32f(kv.w);
        vT[d4 + 0][n] = tf32f(vv.x); vT[d4 + 1][n] = tf32f(vv.y);
        vT[d4 + 2][n] = tf32f(vv.z); vT[d4 + 3][n] = tf32f(vv.w);
    }
    __syncthreads();

    // ---- S = Q·K^T via mma: warp computes rows [wrow, wrow+16), cols [0,56)
    float c[7][4];
    #pragma unroll
    for (int nt = 0; nt < 7; nt++)
        #pragma unroll
        for (int l = 0; l < 4; l++) c[nt][l] = 0.f;

    float4 alo[2], ahi[2];
    #pragma unroll
    for (int cc = 0; cc < 2; cc++) {
        alo[cc] = *(const float4*)&Qs[wrow + grp][cc * 16 + 4 * tig];
        ahi[cc] = *(const float4*)&Qs[wrow + grp + 8][cc * 16 + 4 * tig];
    }
    #pragma unroll
    for (int nt = 0; nt < 7; nt++) {
        #pragma unroll
        for (int cc = 0; cc < 2; cc++) {
            float4 bv = *(const float4*)&Ks[nt * 8 + grp][cc * 16 + 4 * tig];
            mma_tf32(c[nt],
                     __float_as_uint(alo[cc].x), __float_as_uint(ahi[cc].x),
                     __float_as_uint(alo[cc].y), __float_as_uint(ahi[cc].y),
                     __float_as_uint(bv.x), __float_as_uint(bv.y));
            mma_tf32(c[nt],
                     __float_as_uint(alo[cc].z), __float_as_uint(ahi[cc].z),
                     __float_as_uint(alo[cc].w), __float_as_uint(ahi[cc].w),
                     __float_as_uint(bv.z), __float_as_uint(bv.w));
        }
    }

    // ---- Add bias + mask, enforce validity
    const int i0 = wrow + grp, i1 = i0 + 8;
    const float* mrow = mask + (size_t)b * NTOK * NTOK;
    const float* brow = bias + h * NTOK * NTOK;
    #pragma unroll
    for (int nt = 0; nt < 7; nt++) {
        int j0 = nt * 8 + 2 * tig;
        int j1 = j0 + 1;
        bool vi0 = i0 < NTOK, vi1 = i1 < NTOK;
        bool vj0 = j0 < NTOK, vj1 = j1 < NTOK;
        c[nt][0] = (vi0 && vj0) ? c[nt][0] + brow[i0 * NTOK + j0] + mrow[i0 * NTOK + j0] : -1e30f;
        c[nt][1] = (vi0 && vj1) ? c[nt][1] + brow[i0 * NTOK + j1] + mrow[i0 * NTOK + j1] : -1e30f;
        c[nt][2] = (vi1 && vj0) ? c[nt][2] + brow[i1 * NTOK + j0] + mrow[i1 * NTOK + j0] : -1e30f;
        c[nt][3] = (vi1 && vj1) ? c[nt][3] + brow[i1 * NTOK + j1] + mrow[i1 * NTOK + j1] : -1e30f;
    }

    // ---- Register-resident softmax (reduce across 4 tig lanes, rows i0 & i1)
    float m0 = -1e30f, m1 = -1e30f;
    #pragma unroll
    for (int nt = 0; nt < 7; nt++) {
        m0 = fmaxf(m0, fmaxf(c[nt][0], c[nt][1]));
        m1 = fmaxf(m1, fmaxf(c[nt][2], c[nt][3]));
    }
    m0 = fmaxf(m0, __shfl_xor_sync(0xffffffffu, m0, 1));
    m0 = fmaxf(m0, __shfl_xor_sync(0xffffffffu, m0, 2));
    m1 = fmaxf(m1, __shfl_xor_sync(0xffffffffu, m1, 1));
    m1 = fmaxf(m1, __shfl_xor_sync(0xffffffffu, m1, 2));

    float s0 = 0.f, s1 = 0.f;
    #pragma unroll
    for (int nt = 0; nt < 7; nt++) {
        c[nt][0] = __expf(c[nt][0] - m0); s0 += c[nt][0];
        c[nt][1] = __expf(c[nt][1] - m0); s0 += c[nt][1];
        c[nt][2] = __expf(c[nt][2] - m1); s1 += c[nt][2];
        c[nt][3] = __expf(c[nt][3] - m1); s1 += c[nt][3];
    }
    s0 += __shfl_xor_sync(0xffffffffu, s0, 1);
    s0 += __shfl_xor_sync(0xffffffffu, s0, 2);
    s1 += __shfl_xor_sync(0xffffffffu, s1, 1);
    s1 += __shfl_xor_sync(0xffffffffu, s1, 2);
    float inv0 = 1.f / s0, inv1 = 1.f / s1;

    #pragma unroll
    for (int nt = 0; nt < 7; nt++) {
        float2 p0 = make_float2(tf32f(c[nt][0] * inv0), tf32f(c[nt][1] * inv0));
        float2 p1 = make_float2(tf32f(c[nt][2] * inv1), tf32f(c[nt][3] * inv1));
        *(float2*)&sT[i0][nt * 8 + 2 * tig] = p0;
        *(float2*)&sT[i1][nt * 8 + 2 * tig] = p1;
    }
    __syncwarp();

    // ---- O = P·V via mma: warp rows [wrow,wrow+16), d in [0,32)
    float2 pLo[7], pHi[7];
    #pragma unroll
    for (int kk = 0; kk < 7; kk++) {
        pLo[kk] = *(const float2*)&sT[i0][kk * 8 + 2 * tig];
        pHi[kk] = *(const float2*)&sT[i1][kk * 8 + 2 * tig];
    }
    #pragma unroll
    for (int dt = 0; dt < 4; dt++) {
        float o[4] = {0.f, 0.f, 0.f, 0.f};
        #pragma unroll
        for (int kk = 0; kk < 7; kk++) {
            float2 bv = *(const float2*)&vT[dt * 8 + grp][kk * 8 + 2 * tig];
            mma_tf32(o,
                     __float_as_uint(pLo[kk].x), __float_as_uint(pHi[kk].x),
                     __float_as_uint(pLo[kk].y), __float_as_uint(pHi[kk].y),
                     __float_as_uint(bv.x), __float_as_uint(bv.y));
        }
        int dcol = h * HD + dt * 8 + 2 * tig;
        if (i0 < NTOK) {
            float2 v = make_float2(tf32f(o[0]), tf32f(o[1]));   // pre-round for proj-A
            *(float2*)&out[((size_t)b * NTOK + i0) * DIM + dcol] = v;
        }
        if (i1 < NTOK) {
            float2 v = make_float2(tf32f(o[2]), tf32f(o[3]));
            *(float2*)&out[((size_t)b * NTOK + i1) * DIM + dcol] = v;
        }
    }
}

// ---------------------------------------------------------------------------
extern "C" void kernel_launch(void* const* d_in, const int* in_sizes, int n_in,
                              void* d_out, int out_size)
{
    const float* x      = (const float*)d_in[0];
    const float* mask   = (const float*)d_in[1];
    const float* qkv_w  = (const float*)d_in[2];
    const float* qkv_b  = (const float*)d_in[3];
    const float* rpb    = (const float*)d_in[4];
    const float* proj_w = (const float*)d_in[5];
    const float* proj_b = (const float*)d_in[6];
    float* out = (float*)d_out;

    float *qkv_buf, *attn_buf, *wT1, *wT2, *bias_buf;
    cudaGetSymbolAddress((void**)&qkv_buf, g_qkv);
    cudaGetSymbolAddress((void**)&attn_buf, g_attn);
    cudaGetSymbolAddress((void**)&wT1, g_wT1);
    cudaGetSymbolAddress((void**)&wT2, g_wT2);
    cudaGetSymbolAddress((void**)&bias_buf, g_bias);

    cudaFuncSetAttribute(gemm_tf32_v3<true, true>,
                         cudaFuncAttributeMaxDynamicSharedMemorySize, GEMM_SMEM);
    cudaFuncSetAttribute(gemm_tf32_v3<false, false>,
                         cudaFuncAttributeMaxDynamicSharedMemorySize, GEMM_SMEM);

    // 0) Pre-passes (tiny)
    transpose_kernel<<<(DIM * QKV_N + 255) / 256, 256>>>(qkv_w, wT1, DIM, QKV_N);
    transpose_kernel<<<(DIM * DIM + 255) / 256, 256>>>(proj_w, wT2, DIM, DIM);
    bias_expand_kernel<<<(NH * NTOK * NTOK + 255) / 256, 256>>>(rpb, bias_buf);

    // 1) QKV GEMM (output pre-rounded to tf32 for attention consumption)
    gemm_tf32_v3<true, true><<<dim3(QKV_N / BN, MTOK / BM), 256, GEMM_SMEM>>>(
        x, wT1, qkv_b, qkv_buf, QKV_N);

    // 2) Fused window attention (tensor-core S and PV, register softmax)
    attn_v3<<<BATCH * NH, 128>>>(qkv_buf, mask, bias_buf, attn_buf);

    // 3) Proj GEMM (A already tf32-rounded; final output full fp32)
    gemm_tf32_v3<false, false><<<dim3(DIM / BN, MTOK / BM), 256, GEMM_SMEM>>>(
        attn_buf, wT2, proj_b, out, DIM);
}

// round 5
// speedup vs baseline: 2.6577x; 1.4153x over previous
#include <cuda_runtime.h>
#include <cuda_fp16.h>
#include <cuda_bf16.h>
#include <cstdint>

// Problem constants
#define BATCH   4096
#define NTOK    49
#define DIM     256
#define NH      8
#define HD      32
#define MTOK    (BATCH * NTOK)      // 200704
#define QKV_N   (3 * DIM)           // 768
#define KDIM    256
#define SCALE_F 0.17677669529663687f

// Scratch (device globals)
__device__ __half g_xh[(size_t)MTOK * DIM];     // x in fp16
__device__ __half g_qkvh[(size_t)MTOK * QKV_N]; // qkv in fp16 (308 MB)
__device__ __half g_attnh[(size_t)MTOK * DIM];  // attn out in fp16
__device__ __half g_w1h[QKV_N * DIM];           // qkv_w^T fp16 [768][256]
__device__ __half g_w2h[DIM * DIM];             // proj_w^T fp16 [256][256]
__device__ float  g_bias[NH * NTOK * NTOK];     // expanded rpb

__device__ __forceinline__ uint32_t f2tf32(float x) {
    uint32_t r;
    asm("cvt.rna.tf32.f32 %0, %1;" : "=r"(r) : "f"(x));
    return r;
}
__device__ __forceinline__ float tf32f(float x) { return __uint_as_float(f2tf32(x)); }

// tf32 m16n8k8 (attention)
__device__ __forceinline__ void mma_tf32(float c[4], uint32_t a0, uint32_t a1,
                                         uint32_t a2, uint32_t a3,
                                         uint32_t b0, uint32_t b1) {
    asm volatile(
        "mma.sync.aligned.m16n8k8.row.col.f32.tf32.tf32.f32 "
        "{%0,%1,%2,%3},{%4,%5,%6,%7},{%8,%9},{%0,%1,%2,%3};"
        : "+f"(c[0]), "+f"(c[1]), "+f"(c[2]), "+f"(c[3])
        : "r"(a0), "r"(a1), "r"(a2), "r"(a3), "r"(b0), "r"(b1));
}

// fp16 m16n8k16 (GEMMs), fp32 accumulate
__device__ __forceinline__ void mma_f16(float c[4], uint32_t a0, uint32_t a1,
                                        uint32_t a2, uint32_t a3,
                                        uint32_t b0, uint32_t b1) {
    asm volatile(
        "mma.sync.aligned.m16n8k16.row.col.f32.f16.f16.f32 "
        "{%0,%1,%2,%3},{%4,%5,%6,%7},{%8,%9},{%0,%1,%2,%3};"
        : "+f"(c[0]), "+f"(c[1]), "+f"(c[2]), "+f"(c[3])
        : "r"(a0), "r"(a1), "r"(a2), "r"(a3), "r"(b0), "r"(b1));
}

__device__ __forceinline__ void cp_async16(void* smem_dst, const void* gptr) {
    uint32_t s = (uint32_t)__cvta_generic_to_shared(smem_dst);
    asm volatile("cp.async.cg.shared.global [%0], [%1], 16;\n" :: "r"(s), "l"(gptr));
}
#define CP_COMMIT()  asm volatile("cp.async.commit_group;\n" ::: "memory")
#define CP_WAIT(n)   asm volatile("cp.async.wait_group %0;\n" :: "n"(n) : "memory")

// ---------------------------------------------------------------------------
// Pre-passes
// ---------------------------------------------------------------------------
__global__ void f2h_kernel(const float* __restrict__ in, __half* __restrict__ out,
                           int n4) {
    int i = blockIdx.x * 256 + threadIdx.x;
    if (i < n4) {
        float4 v = ((const float4*)in)[i];
        __half2* o = (__half2*)out;
        o[2 * i]     = __floats2half2_rn(v.x, v.y);
        o[2 * i + 1] = __floats2half2_rn(v.z, v.w);
    }
}

__global__ void transpose_h_kernel(const float* __restrict__ in, __half* __restrict__ out,
                                   int R, int C) {
    int idx = blockIdx.x * 256 + threadIdx.x;
    if (idx < R * C) {
        int r = idx / C, c = idx - r * C;
        out[c * R + r] = __float2half_rn(in[idx]);
    }
}

__global__ void bias_expand_kernel(const float* __restrict__ rpb, float* __restrict__ bias) {
    int idx = blockIdx.x * 256 + threadIdx.x;
    if (idx < NH * NTOK * NTOK) {
        int h = idx / (NTOK * NTOK), r = idx % (NTOK * NTOK);
        int i = r / NTOK, j = r % NTOK;
        int ri = i / 7, ci = i - ri * 7;
        int rj = j / 7, cj = j - rj * 7;
        int ridx = (ri - rj + 6) * 13 + (ci - cj + 6);
        bias[idx] = rpb[ridx * NH + h];
    }
}

// ---------------------------------------------------------------------------
// FP16 GEMM: C[M,N] = A[M,256] * BT[N,256]^T + bias[N]
// 128x128 tile, BK=32 halves, 4-stage cp.async, 8 warps (2x4), warp 64x32.
// Tiles stored [row][32 halves] (64 B rows, no pad): per-thread fragments are
// single conflict-free LDS.128 via k-permutation (A and B permuted identically).
// ---------------------------------------------------------------------------
#define BKH 32
#define TILE_BYTES (128 * 64)           // 8192
#define STAGE_BYTES (2 * TILE_BYTES)    // 16384
#define HSTAGES 4
#define GEMM_SMEM_H (HSTAGES * STAGE_BYTES)  // 65536

template<typename OutT>
__device__ __forceinline__ void store2(OutT* p, float a, float b);
template<> __device__ __forceinline__ void store2<float>(float* p, float a, float b) {
    p[0] = a; p[1] = b;
}
template<> __device__ __forceinline__ void store2<__half>(__half* p, float a, float b) {
    *(__half2*)p = __floats2half2_rn(a, b);
}

template<typename OutT>
__global__ __launch_bounds__(256, 2) void gemm_h(
    const __half* __restrict__ A, const __half* __restrict__ BT,
    const float* __restrict__ bias, OutT* __restrict__ C, int N)
{
    extern __shared__ __align__(128) char smem[];

    const int tid  = threadIdx.x;
    const int lane = tid & 31;
    const int warp = tid >> 5;
    const int wm   = warp & 1;
    const int wn   = warp >> 1;
    const int bm   = blockIdx.y * 128;
    const int bn   = blockIdx.x * 128;
    const int tig  = lane & 3;
    const int grp  = lane >> 2;

    float c[4][4][4];
    #pragma unroll
    for (int mi = 0; mi < 4; mi++)
        #pragma unroll
        for (int ni = 0; ni < 4; ni++)
            #pragma unroll
            for (int r = 0; r < 4; r++) c[mi][ni][r] = 0.f;

    auto load_stage = [&](int slot, int kt) {
        char* ab = smem + slot * STAGE_BYTES;
        char* bb = ab + TILE_BYTES;
        const __half* ag = A  + (size_t)bm * KDIM + kt * BKH;
        const __half* bg = BT + (size_t)bn * KDIM + kt * BKH;
        #pragma unroll
        for (int j = 0; j < 2; j++) {
            int sgi = tid + j * 256;        // 0..511
            int r   = sgi >> 2;
            int cc  = sgi & 3;
            cp_async16(ab + r * 64 + cc * 16, ag + (size_t)r * KDIM + cc * 8);
            cp_async16(bb + r * 64 + cc * 16, bg + (size_t)r * KDIM + cc * 8);
        }
    };

    const int ITERS = KDIM / BKH;   // 8
    #pragma unroll
    for (int p = 0; p < HSTAGES - 1; p++) { load_stage(p, p); CP_COMMIT(); }

    for (int it = 0; it < ITERS; it++) {
        CP_WAIT(HSTAGES - 2);
        __syncthreads();

        int nk = it + HSTAGES - 1;
        if (nk < ITERS) load_stage(nk & (HSTAGES - 1), nk);
        CP_COMMIT();

        const char* as = smem + (it & (HSTAGES - 1)) * STAGE_BYTES;
        const char* bs = as + TILE_BYTES;

        // A fragments: 8 conflict-free LDS.128
        uint4 ra[4], rb[4];
        #pragma unroll
        for (int mi = 0; mi < 4; mi++) {
            int row = wm * 64 + mi * 16 + grp;
            ra[mi] = *(const uint4*)(as + row * 64 + tig * 16);
            rb[mi] = *(const uint4*)(as + (row + 8) * 64 + tig * 16);
        }
        // B fragments + MMAs
        #pragma unroll
        for (int ni = 0; ni < 4; ni++) {
            int col = wn * 32 + ni * 8 + grp;
            uint4 sb = *(const uint4*)(bs + col * 64 + tig * 16);
            #pragma unroll
            for (int mi = 0; mi < 4; mi++) {
                mma_f16(c[mi][ni], ra[mi].x, rb[mi].x, ra[mi].y, rb[mi].y, sb.x, sb.y);
                mma_f16(c[mi][ni], ra[mi].z, rb[mi].z, ra[mi].w, rb[mi].w, sb.z, sb.w);
            }
        }
    }

    // Epilogue: C = acc + bias
    #pragma unroll
    for (int mi = 0; mi < 4; mi++) {
        int row0 = bm + wm * 64 + mi * 16 + grp;
        #pragma unroll
        for (int ni = 0; ni < 4; ni++) {
            int col0 = bn + wn * 32 + ni * 8 + tig * 2;
            float bi0 = bias[col0], bi1 = bias[col0 + 1];
            store2(C + (size_t)row0 * N + col0,       c[mi][ni][0] + bi0, c[mi][ni][1] + bi1);
            store2(C + (size_t)(row0 + 8) * N + col0, c[mi][ni][2] + bi0, c[mi][ni][3] + bi1);
        }
    }
}

// ---------------------------------------------------------------------------
// Fused window attention: round-3 structure, fp16 I/O.
// One block per (b,h), 4 warps, tf32 warp MMA, register softmax.
// ---------------------------------------------------------------------------
#define SQ 36
#define SJ 68

__global__ __launch_bounds__(128) void attn_h(
    const __half* __restrict__ qkv, const float* __restrict__ mask,
    const float* __restrict__ bias, __half* __restrict__ out)
{
    __shared__ float Qs[64][SQ];
    __shared__ float Ks[56][SQ];
    __shared__ float vT[32][SJ];
    __shared__ float sT[64][SJ];

    const int bh   = blockIdx.x;
    const int h    = bh & (NH - 1);
    const int b    = bh >> 3;
    const int tid  = threadIdx.x;
    const int lane = tid & 31;
    const int warp = tid >> 5;
    const int tig  = lane & 3;
    const int grp  = lane >> 2;
    const int wrow = warp * 16;

    for (int idx = tid; idx < 15 * SQ; idx += 128) Qs[49 + idx / SQ][idx % SQ] = 0.f;
    for (int idx = tid; idx < 7 * SQ;  idx += 128) Ks[49 + idx / SQ][idx % SQ] = 0.f;
    for (int idx = tid; idx < 32 * 20; idx += 128) vT[idx / 20][48 + idx % 20] = 0.f;

    const __half* basep = qkv + (size_t)b * NTOK * QKV_N + h * HD;
    for (int idx = tid; idx < NTOK * 8; idx += 128) {
        int n = idx >> 3, d4 = (idx & 7) * 4;
        const __half* t = basep + (size_t)n * QKV_N + d4;
        float2 q01 = __half22float2(*(const __half2*)(t));
        float2 q23 = __half22float2(*(const __half2*)(t + 2));
        float2 k01 = __half22float2(*(const __half2*)(t + DIM));
        float2 k23 = __half22float2(*(const __half2*)(t + DIM + 2));
        float2 v01 = __half22float2(*(const __half2*)(t + 2 * DIM));
        float2 v23 = __half22float2(*(const __half2*)(t + 2 * DIM + 2));
        // q scaled + rounded to tf32; k/v are fp16-exact in tf32 already
        Qs[n][d4 + 0] = tf32f(q01.x * SCALE_F); Qs[n][d4 + 1] = tf32f(q01.y * SCALE_F);
        Qs[n][d4 + 2] = tf32f(q23.x * SCALE_F); Qs[n][d4 + 3] = tf32f(q23.y * SCALE_F);
        Ks[n][d4 + 0] = k01.x; Ks[n][d4 + 1] = k01.y;
        Ks[n][d4 + 2] = k23.x; Ks[n][d4 + 3] = k23.y;
        vT[d4 + 0][n] = v01.x; vT[d4 + 1][n] = v01.y;
        vT[d4 + 2][n] = v23.x; vT[d4 + 3][n] = v23.y;
    }
    __syncthreads();

    float c[7][4];
    #pragma unroll
    for (int nt = 0; nt < 7; nt++)
        #pragma unroll
        for (int l = 0; l < 4; l++) c[nt][l] = 0.f;

    float4 alo[2], ahi[2];
    #pragma unroll
    for (int cc = 0; cc < 2; cc++) {
        alo[cc] = *(const float4*)&Qs[wrow + grp][cc * 16 + 4 * tig];
        ahi[cc] = *(const float4*)&Qs[wrow + grp + 8][cc * 16 + 4 * tig];
    }
    #pragma unroll
    for (int nt = 0; nt < 7; nt++) {
        #pragma unroll
        for (int cc = 0; cc < 2; cc++) {
            float4 bv = *(const float4*)&Ks[nt * 8 + grp][cc * 16 + 4 * tig];
            mma_tf32(c[nt],
                     __float_as_uint(alo[cc].x), __float_as_uint(ahi[cc].x),
                     __float_as_uint(alo[cc].y), __float_as_uint(ahi[cc].y),
                     __float_as_uint(bv.x), __float_as_uint(bv.y));
            mma_tf32(c[nt],
                     __float_as_uint(alo[cc].z), __float_as_uint(ahi[cc].z),
                     __float_as_uint(alo[cc].w), __float_as_uint(ahi[cc].w),
                     __float_as_uint(bv.z), __float_as_uint(bv.w));
        }
    }

    const int i0 = wrow + grp, i1 = i0 + 8;
    const float* mrow = mask + (size_t)b * NTOK * NTOK;
    const float* brow = bias + h * NTOK * NTOK;
    #pragma unroll
    for (int nt = 0; nt < 7; nt++) {
        int j0 = nt * 8 + 2 * tig;
        int j1 = j0 + 1;
        bool vi0 = i0 < NTOK, vi1 = i1 < NTOK;
        bool vj0 = j0 < NTOK, vj1 = j1 < NTOK;
        c[nt][0] = (vi0 && vj0) ? c[nt][0] + brow[i0 * NTOK + j0] + mrow[i0 * NTOK + j0] : -1e30f;
        c[nt][1] = (vi0 && vj1) ? c[nt][1] + brow[i0 * NTOK + j1] + mrow[i0 * NTOK + j1] : -1e30f;
        c[nt][2] = (vi1 && vj0) ? c[nt][2] + brow[i1 * NTOK + j0] + mrow[i1 * NTOK + j0] : -1e30f;
        c[nt][3] = (vi1 && vj1) ? c[nt][3] + brow[i1 * NTOK + j1] + mrow[i1 * NTOK + j1] : -1e30f;
    }

    float m0 = -1e30f, m1 = -1e30f;
    #pragma unroll
    for (int nt = 0; nt < 7; nt++) {
        m0 = fmaxf(m0, fmaxf(c[nt][0], c[nt][1]));
        m1 = fmaxf(m1, fmaxf(c[nt][2], c[nt][3]));
    }
    m0 = fmaxf(m0, __shfl_xor_sync(0xffffffffu, m0, 1));
    m0 = fmaxf(m0, __shfl_xor_sync(0xffffffffu, m0, 2));
    m1 = fmaxf(m1, __shfl_xor_sync(0xffffffffu, m1, 1));
    m1 = fmaxf(m1, __shfl_xor_sync(0xffffffffu, m1, 2));

    float s0 = 0.f, s1 = 0.f;
    #pragma unroll
    for (int nt = 0; nt < 7; nt++) {
        c[nt][0] = __expf(c[nt][0] - m0); s0 += c[nt][0];
        c[nt][1] = __expf(c[nt][1] - m0); s0 += c[nt][1];
        c[nt][2] = __expf(c[nt][2] - m1); s1 += c[nt][2];
        c[nt][3] = __expf(c[nt][3] - m1); s1 += c[nt][3];
    }
    s0 += __shfl_xor_sync(0xffffffffu, s0, 1);
    s0 += __shfl_xor_sync(0xffffffffu, s0, 2);
    s1 += __shfl_xor_sync(0xffffffffu, s1, 1);
    s1 += __shfl_xor_sync(0xffffffffu, s1, 2);
    float inv0 = 1.f / s0, inv1 = 1.f / s1;

    #pragma unroll
    for (int nt = 0; nt < 7; nt++) {
        float2 p0 = make_float2(tf32f(c[nt][0] * inv0), tf32f(c[nt][1] * inv0));
        float2 p1 = make_float2(tf32f(c[nt][2] * inv1), tf32f(c[nt][3] * inv1));
        *(float2*)&sT[i0][nt * 8 + 2 * tig] = p0;
        *(float2*)&sT[i1][nt * 8 + 2 * tig] = p1;
    }
    __syncwarp();

    float2 pLo[7], pHi[7];
    #pragma unroll
    for (int kk = 0; kk < 7; kk++) {
        pLo[kk] = *(const float2*)&sT[i0][kk * 8 + 2 * tig];
        pHi[kk] = *(const float2*)&sT[i1][kk * 8 + 2 * tig];
    }
    #pragma unroll
    for (int dt = 0; dt < 4; dt++) {
        float o[4] = {0.f, 0.f, 0.f, 0.f};
        #pragma unroll
        for (int kk = 0; kk < 7; kk++) {
            float2 bv = *(const float2*)&vT[dt * 8 + grp][kk * 8 + 2 * tig];
            mma_tf32(o,
                     __float_as_uint(pLo[kk].x), __float_as_uint(pHi[kk].x),
                     __float_as_uint(pLo[kk].y), __float_as_uint(pHi[kk].y),
                     __float_as_uint(bv.x), __float_as_uint(bv.y));
        }
        int dcol = h * HD + dt * 8 + 2 * tig;
        if (i0 < NTOK)
            *(__half2*)&out[((size_t)b * NTOK + i0) * DIM + dcol] = __floats2half2_rn(o[0], o[1]);
        if (i1 < NTOK)
            *(__half2*)&out[((size_t)b * NTOK + i1) * DIM + dcol] = __floats2half2_rn(o[2], o[3]);
    }
}

// ---------------------------------------------------------------------------
extern "C" void kernel_launch(void* const* d_in, const int* in_sizes, int n_in,
                              void* d_out, int out_size)
{
    const float* x      = (const float*)d_in[0];
    const float* mask   = (const float*)d_in[1];
    const float* qkv_w  = (const float*)d_in[2];
    const float* qkv_b  = (const float*)d_in[3];
    const float* rpb    = (const float*)d_in[4];
    const float* proj_w = (const float*)d_in[5];
    const float* proj_b = (const float*)d_in[6];
    float* out = (float*)d_out;

    __half *xh, *qkvh, *attnh, *w1h, *w2h;
    float *bias_buf;
    cudaGetSymbolAddress((void**)&xh, g_xh);
    cudaGetSymbolAddress((void**)&qkvh, g_qkvh);
    cudaGetSymbolAddress((void**)&attnh, g_attnh);
    cudaGetSymbolAddress((void**)&w1h, g_w1h);
    cudaGetSymbolAddress((void**)&w2h, g_w2h);
    cudaGetSymbolAddress((void**)&bias_buf, g_bias);

    cudaFuncSetAttribute(gemm_h<__half>,
                         cudaFuncAttributeMaxDynamicSharedMemorySize, GEMM_SMEM_H);
    cudaFuncSetAttribute(gemm_h<float>,
                         cudaFuncAttributeMaxDynamicSharedMemorySize, GEMM_SMEM_H);

    // 0) Pre-passes: x -> fp16; weights -> fp16 transposed; expand bias
    int n4 = MTOK * DIM / 4;
    f2h_kernel<<<(n4 + 255) / 256, 256>>>(x, xh, n4);
    transpose_h_kernel<<<(DIM * QKV_N + 255) / 256, 256>>>(qkv_w, w1h, DIM, QKV_N);
    transpose_h_kernel<<<(DIM * DIM + 255) / 256, 256>>>(proj_w, w2h, DIM, DIM);
    bias_expand_kernel<<<(NH * NTOK * NTOK + 255) / 256, 256>>>(rpb, bias_buf);

    // 1) QKV GEMM (fp16 in, fp16 out + fp32 bias)
    gemm_h<__half><<<dim3(QKV_N / 128, MTOK / 128), 256, GEMM_SMEM_H>>>(
        xh, w1h, qkv_b, qkvh, QKV_N);

    // 2) Fused window attention (fp16 I/O, tf32 core)
    attn_h<<<BATCH * NH, 128>>>(qkvh, mask, bias_buf, attnh);

    // 3) Proj GEMM (fp16 in, fp32 out)
    gemm_h<float><<<dim3(DIM / 128, MTOK / 128), 256, GEMM_SMEM_H>>>(
        attnh, w2h, proj_b, out, DIM);
}

// round 6
// speedup vs baseline: 3.0894x; 1.1624x over previous
#include <cuda_runtime.h>
#include <cuda_fp16.h>
#include <cstdint>

// Problem constants
#define BATCH   4096
#define NTOK    49
#define DIM     256
#define NH      8
#define HD      32
#define MTOK    (BATCH * NTOK)      // 200704
#define QKV_N   (3 * DIM)           // 768
#define KDIM    256
#define SCALE_F 0.17677669529663687f

// Scratch (device globals)
__device__ __half g_xh[(size_t)MTOK * DIM];     // x in fp16
__device__ __half g_qkvh[(size_t)MTOK * QKV_N]; // qkv in fp16 (308 MB)
__device__ __half g_w1h[QKV_N * DIM];           // qkv_w^T fp16 [768][256]
__device__ __half g_w2h[DIM * DIM];             // proj_w^T fp16 [256][256]
__device__ float  g_bias[NH * NTOK * NTOK];     // expanded rpb [h][i][j]

// fp16 m16n8k16 mma, fp32 accumulate
__device__ __forceinline__ void mma_f16(float c[4], uint32_t a0, uint32_t a1,
                                        uint32_t a2, uint32_t a3,
                                        uint32_t b0, uint32_t b1) {
    asm volatile(
        "mma.sync.aligned.m16n8k16.row.col.f32.f16.f16.f32 "
        "{%0,%1,%2,%3},{%4,%5,%6,%7},{%8,%9},{%0,%1,%2,%3};"
        : "+f"(c[0]), "+f"(c[1]), "+f"(c[2]), "+f"(c[3])
        : "r"(a0), "r"(a1), "r"(a2), "r"(a3), "r"(b0), "r"(b1));
}

__device__ __forceinline__ void cp_async16(void* smem_dst, const void* gptr) {
    uint32_t s = (uint32_t)__cvta_generic_to_shared(smem_dst);
    asm volatile("cp.async.cg.shared.global [%0], [%1], 16;\n" :: "r"(s), "l"(gptr));
}
#define CP_COMMIT()  asm volatile("cp.async.commit_group;\n" ::: "memory")
#define CP_WAIT(n)   asm volatile("cp.async.wait_group %0;\n" :: "n"(n) : "memory")

__device__ __forceinline__ uint32_t pack_h2(float a, float b) {
    __half2 h = __floats2half2_rn(a, b);
    return *(uint32_t*)&h;
}

// ---------------------------------------------------------------------------
// Pre-passes
// ---------------------------------------------------------------------------
__global__ void f2h_kernel(const float* __restrict__ in, __half* __restrict__ out,
                           int n4) {
    int i = blockIdx.x * 256 + threadIdx.x;
    if (i < n4) {
        float4 v = ((const float4*)in)[i];
        __half2* o = (__half2*)out;
        o[2 * i]     = __floats2half2_rn(v.x, v.y);
        o[2 * i + 1] = __floats2half2_rn(v.z, v.w);
    }
}

__global__ void transpose_h_kernel(const float* __restrict__ in, __half* __restrict__ out,
                                   int R, int C) {
    int idx = blockIdx.x * 256 + threadIdx.x;
    if (idx < R * C) {
        int r = idx / C, c = idx - r * C;
        out[c * R + r] = __float2half_rn(in[idx]);
    }
}

__global__ void bias_expand_kernel(const float* __restrict__ rpb, float* __restrict__ bias) {
    int idx = blockIdx.x * 256 + threadIdx.x;
    if (idx < NH * NTOK * NTOK) {
        int h = idx / (NTOK * NTOK), r = idx % (NTOK * NTOK);
        int i = r / NTOK, j = r % NTOK;
        int ri = i / 7, ci = i - ri * 7;
        int rj = j / 7, cj = j - rj * 7;
        int ridx = (ri - rj + 6) * 13 + (ci - cj + 6);
        bias[idx] = rpb[ridx * NH + h];
    }
}

// ---------------------------------------------------------------------------
// FP16 QKV GEMM (validated round-5 kernel, unchanged)
// ---------------------------------------------------------------------------
#define BKH 32
#define TILE_BYTES (128 * 64)
#define STAGE_BYTES (2 * TILE_BYTES)
#define HSTAGES 4
#define GEMM_SMEM_H (HSTAGES * STAGE_BYTES)

__global__ __launch_bounds__(256, 2) void gemm_h(
    const __half* __restrict__ A, const __half* __restrict__ BT,
    const float* __restrict__ bias, __half* __restrict__ C, int N)
{
    extern __shared__ __align__(128) char smem[];

    const int tid  = threadIdx.x;
    const int lane = tid & 31;
    const int warp = tid >> 5;
    const int wm   = warp & 1;
    const int wn   = warp >> 1;
    const int bm   = blockIdx.y * 128;
    const int bn   = blockIdx.x * 128;
    const int tig  = lane & 3;
    const int grp  = lane >> 2;

    float c[4][4][4];
    #pragma unroll
    for (int mi = 0; mi < 4; mi++)
        #pragma unroll
        for (int ni = 0; ni < 4; ni++)
            #pragma unroll
            for (int r = 0; r < 4; r++) c[mi][ni][r] = 0.f;

    auto load_stage = [&](int slot, int kt) {
        char* ab = smem + slot * STAGE_BYTES;
        char* bb = ab + TILE_BYTES;
        const __half* ag = A  + (size_t)bm * KDIM + kt * BKH;
        const __half* bg = BT + (size_t)bn * KDIM + kt * BKH;
        #pragma unroll
        for (int j = 0; j < 2; j++) {
            int sgi = tid + j * 256;
            int r   = sgi >> 2;
            int cc  = sgi & 3;
            cp_async16(ab + r * 64 + cc * 16, ag + (size_t)r * KDIM + cc * 8);
            cp_async16(bb + r * 64 + cc * 16, bg + (size_t)r * KDIM + cc * 8);
        }
    };

    const int ITERS = KDIM / BKH;
    #pragma unroll
    for (int p = 0; p < HSTAGES - 1; p++) { load_stage(p, p); CP_COMMIT(); }

    for (int it = 0; it < ITERS; it++) {
        CP_WAIT(HSTAGES - 2);
        __syncthreads();

        int nk = it + HSTAGES - 1;
        if (nk < ITERS) load_stage(nk & (HSTAGES - 1), nk);
        CP_COMMIT();

        const char* as = smem + (it & (HSTAGES - 1)) * STAGE_BYTES;
        const char* bs = as + TILE_BYTES;

        uint4 ra[4], rb[4];
        #pragma unroll
        for (int mi = 0; mi < 4; mi++) {
            int row = wm * 64 + mi * 16 + grp;
            ra[mi] = *(const uint4*)(as + row * 64 + tig * 16);
            rb[mi] = *(const uint4*)(as + (row + 8) * 64 + tig * 16);
        }
        #pragma unroll
        for (int ni = 0; ni < 4; ni++) {
            int col = wn * 32 + ni * 8 + grp;
            uint4 sb = *(const uint4*)(bs + col * 64 + tig * 16);
            #pragma unroll
            for (int mi = 0; mi < 4; mi++) {
                mma_f16(c[mi][ni], ra[mi].x, rb[mi].x, ra[mi].y, rb[mi].y, sb.x, sb.y);
                mma_f16(c[mi][ni], ra[mi].z, rb[mi].z, ra[mi].w, rb[mi].w, sb.z, sb.w);
            }
        }
    }

    #pragma unroll
    for (int mi = 0; mi < 4; mi++) {
        int row0 = bm + wm * 64 + mi * 16 + grp;
        #pragma unroll
        for (int ni = 0; ni < 4; ni++) {
            int col0 = bn + wn * 32 + ni * 8 + tig * 2;
            float bi0 = bias[col0], bi1 = bias[col0 + 1];
            *(__half2*)(C + (size_t)row0 * N + col0) =
                __floats2half2_rn(c[mi][ni][0] + bi0, c[mi][ni][1] + bi1);
            *(__half2*)(C + (size_t)(row0 + 8) * N + col0) =
                __floats2half2_rn(c[mi][ni][2] + bi0, c[mi][ni][3] + bi1);
        }
    }
}

// ---------------------------------------------------------------------------
// Fused attention + projection: one block per window, 512 threads (16 warps).
// Warps (h=wid>>1, sub=wid&1): head h, rows [sub*32, sub*32+32).
// Phases: cp.async qkv -> build vT -> S mma (fp16 k16) -> reg softmax ->
//         PV mma (P stays in regs) -> attn-out to smem (aliases q/k) ->
//         in-block proj GEMM (W2T from L2) -> fp32 out.
// ---------------------------------------------------------------------------
#define RAW_STRIDE 1552                 // bytes per qkv row (768 halves + 8 pad)
#define RAW_BYTES  (NTOK * RAW_STRIDE)  // 76048
#define VT_STRIDE  144                  // bytes per vT row (72 halves)
#define VT_OFF     RAW_BYTES
#define VT_BYTES   (256 * VT_STRIDE)    // 36864
#define AO_STRIDE  576                  // bytes per attn-out row (288 halves)
#define FUSE_SMEM  (VT_OFF + VT_BYTES)  // 112912

__global__ __launch_bounds__(512, 1) void attn_proj_fused(
    const __half* __restrict__ qkv, const float* __restrict__ mask,
    const float* __restrict__ bias, const __half* __restrict__ w2,
    const float* __restrict__ proj_b, float* __restrict__ out)
{
    extern __shared__ __align__(128) char sm[];
    char* vt = sm + VT_OFF;

    const int b    = blockIdx.x;
    const int tid  = threadIdx.x;
    const int lane = tid & 31;
    const int wid  = tid >> 5;
    const int g    = lane >> 2;     // 0..7
    const int q    = lane & 3;      // 0..3

    // ---- Phase 1: async load window qkv [49][768 halves] (row stride 1552B)
    {
        const __half* src = qkv + (size_t)b * NTOK * QKV_N;
        for (int idx = tid; idx < NTOK * 96; idx += 512) {
            int tok = idx / 96, c16 = idx - tok * 96;
            cp_async16(sm + tok * RAW_STRIDE + c16 * 16,
                       src + (size_t)tok * QKV_N + c16 * 8);
        }
        CP_COMMIT();
    }
    // Zero vT while loads fly (covers j-padding 49..63 and beyond)
    for (int idx = tid; idx < VT_BYTES / 4; idx += 512)
        *(uint32_t*)(vt + idx * 4) = 0;
    CP_WAIT(0);
    __syncthreads();

    // ---- Phase 1b: build vT[hd][j] (hd = h*32+d, stride 144B)
    {
        int p = tid >> 1;               // (h,d) pair 0..255
        int half_sel = tid & 1;
        int t0 = half_sel ? 25 : 0;
        int t1 = half_sel ? 49 : 25;
        for (int tok = t0; tok < t1; tok++) {
            __half v = *(const __half*)(sm + tok * RAW_STRIDE + 1024 + p * 2);
            *(__half*)(vt + p * VT_STRIDE + tok * 2) = v;
        }
    }
    __syncthreads();

    // ---- Phase 2: S = Q*K^T per warp (head h, 32 rows)
    const int h   = wid >> 1;
    const int sub = wid & 1;
    const int hoff = h * 64;            // head byte offset within q segment

    float c[2][7][4];
    #pragma unroll
    for (int mi = 0; mi < 2; mi++)
        #pragma unroll
        for (int nt = 0; nt < 7; nt++)
            #pragma unroll
            for (int r = 0; r < 4; r++) c[mi][nt][r] = 0.f;

    uint32_t af[2][2][4];   // [mi][kchunk][a0..a3]
    #pragma unroll
    for (int mi = 0; mi < 2; mi++) {
        int r0 = sub * 32 + mi * 16 + g;
        #pragma unroll
        for (int cc = 0; cc < 2; cc++) {
            const char* base = sm + hoff + cc * 32 + q * 4;
            af[mi][cc][0] = *(const uint32_t*)(base + r0 * RAW_STRIDE);
            af[mi][cc][1] = *(const uint32_t*)(base + (r0 + 8) * RAW_STRIDE);
            af[mi][cc][2] = *(const uint32_t*)(base + r0 * RAW_STRIDE + 16);
            af[mi][cc][3] = *(const uint32_t*)(base + (r0 + 8) * RAW_STRIDE + 16);
        }
    }
    #pragma unroll
    for (int nt = 0; nt < 7; nt++) {
        int j = nt * 8 + g;
        #pragma unroll
        for (int cc = 0; cc < 2; cc++) {
            const char* base = sm + j * RAW_STRIDE + 512 + hoff + cc * 32 + q * 4;
            uint32_t b0 = *(const uint32_t*)(base);
            uint32_t b1 = *(const uint32_t*)(base + 16);
            #pragma unroll
            for (int mi = 0; mi < 2; mi++)
                mma_f16(c[mi][nt], af[mi][cc][0], af[mi][cc][1],
                        af[mi][cc][2], af[mi][cc][3], b0, b1);
        }
    }

    // ---- Phase 3: scale + bias + mask + register softmax (per mi: rows i0,i1)
    const float* mrow = mask + (size_t)b * NTOK * NTOK;
    const float* brow = bias + h * NTOK * NTOK;
    float inv0[2], inv1[2];
    #pragma unroll
    for (int mi = 0; mi < 2; mi++) {
        int i0 = sub * 32 + mi * 16 + g;
        int i1 = i0 + 8;
        bool vi0 = i0 < NTOK, vi1 = i1 < NTOK;
        #pragma unroll
        for (int nt = 0; nt < 7; nt++) {
            int j0 = nt * 8 + 2 * q, j1 = j0 + 1;
            bool vj0 = j0 < NTOK, vj1 = j1 < NTOK;
            c[mi][nt][0] = (vi0 && vj0) ? c[mi][nt][0] * SCALE_F + brow[i0 * NTOK + j0] + mrow[i0 * NTOK + j0] : -1e30f;
            c[mi][nt][1] = (vi0 && vj1) ? c[mi][nt][1] * SCALE_F + brow[i0 * NTOK + j1] + mrow[i0 * NTOK + j1] : -1e30f;
            c[mi][nt][2] = (vi1 && vj0) ? c[mi][nt][2] * SCALE_F + brow[i1 * NTOK + j0] + mrow[i1 * NTOK + j0] : -1e30f;
            c[mi][nt][3] = (vi1 && vj1) ? c[mi][nt][3] * SCALE_F + brow[i1 * NTOK + j1] + mrow[i1 * NTOK + j1] : -1e30f;
        }
        float m0 = -1e30f, m1 = -1e30f;
        #pragma unroll
        for (int nt = 0; nt < 7; nt++) {
            m0 = fmaxf(m0, fmaxf(c[mi][nt][0], c[mi][nt][1]));
            m1 = fmaxf(m1, fmaxf(c[mi][nt][2], c[mi][nt][3]));
        }
        m0 = fmaxf(m0, __shfl_xor_sync(0xffffffffu, m0, 1));
        m0 = fmaxf(m0, __shfl_xor_sync(0xffffffffu, m0, 2));
        m1 = fmaxf(m1, __shfl_xor_sync(0xffffffffu, m1, 1));
        m1 = fmaxf(m1, __shfl_xor_sync(0xffffffffu, m1, 2));
        float s0 = 0.f, s1 = 0.f;
        #pragma unroll
        for (int nt = 0; nt < 7; nt++) {
            c[mi][nt][0] = __expf(c[mi][nt][0] - m0); s0 += c[mi][nt][0];
            c[mi][nt][1] = __expf(c[mi][nt][1] - m0); s0 += c[mi][nt][1];
            c[mi][nt][2] = __expf(c[mi][nt][2] - m1); s1 += c[mi][nt][2];
            c[mi][nt][3] = __expf(c[mi][nt][3] - m1); s1 += c[mi][nt][3];
        }
        s0 += __shfl_xor_sync(0xffffffffu, s0, 1);
        s0 += __shfl_xor_sync(0xffffffffu, s0, 2);
        s1 += __shfl_xor_sync(0xffffffffu, s1, 1);
        s1 += __shfl_xor_sync(0xffffffffu, s1, 2);
        inv0[mi] = 1.f / s0;
        inv1[mi] = 1.f / s1;
    }

    // ---- Pack P into fp16 A-fragments (registers only)
    uint32_t pa[2][4][4];   // [mi][kchunk][a0..a3]
    #pragma unroll
    for (int mi = 0; mi < 2; mi++) {
        #pragma unroll
        for (int ch = 0; ch < 4; ch++) {
            int nt0 = 2 * ch, nt1 = 2 * ch + 1;
            pa[mi][ch][0] = pack_h2(c[mi][nt0][0] * inv0[mi], c[mi][nt0][1] * inv0[mi]);
            pa[mi][ch][1] = pack_h2(c[mi][nt0][2] * inv1[mi], c[mi][nt0][3] * inv1[mi]);
            if (nt1 < 7) {
                pa[mi][ch][2] = pack_h2(c[mi][nt1][0] * inv0[mi], c[mi][nt1][1] * inv0[mi]);
                pa[mi][ch][3] = pack_h2(c[mi][nt1][2] * inv1[mi], c[mi][nt1][3] * inv1[mi]);
            } else {
                pa[mi][ch][2] = 0u;
                pa[mi][ch][3] = 0u;
            }
        }
    }
    __syncthreads();   // all RAW q/k reads complete before AO overwrites

    // ---- Phase 4: PV mma; write attn-out rows into AO (aliases RAW)
    #pragma unroll
    for (int mi = 0; mi < 2; mi++) {
        int i0 = sub * 32 + mi * 16 + g;
        int i1 = i0 + 8;
        #pragma unroll
        for (int ni = 0; ni < 4; ni++) {
            float o[4] = {0.f, 0.f, 0.f, 0.f};
            int vrow = h * 32 + ni * 8 + g;
            #pragma unroll
            for (int ch = 0; ch < 4; ch++) {
                const char* base = vt + vrow * VT_STRIDE + ch * 32 + q * 4;
                uint32_t b0 = *(const uint32_t*)(base);
                uint32_t b1 = *(const uint32_t*)(base + 16);
                mma_f16(o, pa[mi][ch][0], pa[mi][ch][1],
                        pa[mi][ch][2], pa[mi][ch][3], b0, b1);
            }
            int colb = (h * 32 + ni * 8) * 2 + q * 4;
            *(uint32_t*)(sm + i0 * AO_STRIDE + colb) = pack_h2(o[0], o[1]);
            *(uint32_t*)(sm + i1 * AO_STRIDE + colb) = pack_h2(o[2], o[3]);
        }
    }
    __syncthreads();

    // ---- Phase 5: proj GEMM [64x256] = AO[64x256] x W2T[256x256]^T
    const int wm = wid & 1;
    const int wn = wid >> 1;           // 0..7
    float d[2][4][4];
    #pragma unroll
    for (int mi = 0; mi < 2; mi++)
        #pragma unroll
        for (int ni = 0; ni < 4; ni++)
            #pragma unroll
            for (int r = 0; r < 4; r++) d[mi][ni][r] = 0.f;

    #pragma unroll
    for (int cp = 0; cp < 8; cp++) {
        uint4 ra[2], rb[2];
        #pragma unroll
        for (int mi = 0; mi < 2; mi++) {
            int r0 = wm * 32 + mi * 16 + g;
            ra[mi] = *(const uint4*)(sm + r0 * AO_STRIDE + cp * 64 + q * 16);
            rb[mi] = *(const uint4*)(sm + (r0 + 8) * AO_STRIDE + cp * 64 + q * 16);
        }
        #pragma unroll
        for (int ni = 0; ni < 4; ni++) {
            int n = wn * 32 + ni * 8 + g;
            uint4 sb = *(const uint4*)(w2 + (size_t)n * KDIM + cp * 32 + q * 8);
            #pragma unroll
            for (int mi = 0; mi < 2; mi++) {
                mma_f16(d[mi][ni], ra[mi].x, rb[mi].x, ra[mi].y, rb[mi].y, sb.x, sb.y);
                mma_f16(d[mi][ni], ra[mi].z, rb[mi].z, ra[mi].w, rb[mi].w, sb.z, sb.w);
            }
        }
    }

    // ---- Epilogue: + proj_b, fp32 out (valid rows only)
    #pragma unroll
    for (int mi = 0; mi < 2; mi++) {
        int i0 = wm * 32 + mi * 16 + g;
        int i1 = i0 + 8;
        #pragma unroll
        for (int ni = 0; ni < 4; ni++) {
            int n0 = wn * 32 + ni * 8 + 2 * q;
            float2 pb = *(const float2*)(proj_b + n0);
            if (i0 < NTOK) {
                float2 v = make_float2(d[mi][ni][0] + pb.x, d[mi][ni][1] + pb.y);
                *(float2*)(out + ((size_t)b * NTOK + i0) * DIM + n0) = v;
            }
            if (i1 < NTOK) {
                float2 v = make_float2(d[mi][ni][2] + pb.x, d[mi][ni][3] + pb.y);
                *(float2*)(out + ((size_t)b * NTOK + i1) * DIM + n0) = v;
            }
        }
    }
}

// ---------------------------------------------------------------------------
extern "C" void kernel_launch(void* const* d_in, const int* in_sizes, int n_in,
                              void* d_out, int out_size)
{
    const float* x      = (const float*)d_in[0];
    const float* mask   = (const float*)d_in[1];
    const float* qkv_w  = (const float*)d_in[2];
    const float* qkv_b  = (const float*)d_in[3];
    const float* rpb    = (const float*)d_in[4];
    const float* proj_w = (const float*)d_in[5];
    const float* proj_b = (const float*)d_in[6];
    float* out = (float*)d_out;

    __half *xh, *qkvh, *w1h, *w2h;
    float *bias_buf;
    cudaGetSymbolAddress((void**)&xh, g_xh);
    cudaGetSymbolAddress((void**)&qkvh, g_qkvh);
    cudaGetSymbolAddress((void**)&w1h, g_w1h);
    cudaGetSymbolAddress((void**)&w2h, g_w2h);
    cudaGetSymbolAddress((void**)&bias_buf, g_bias);

    cudaFuncSetAttribute(gemm_h,
                         cudaFuncAttributeMaxDynamicSharedMemorySize, GEMM_SMEM_H);
    cudaFuncSetAttribute(attn_proj_fused,
                         cudaFuncAttributeMaxDynamicSharedMemorySize, FUSE_SMEM);

    // 0) Pre-passes
    int n4 = MTOK * DIM / 4;
    f2h_kernel<<<(n4 + 255) / 256, 256>>>(x, xh, n4);
    transpose_h_kernel<<<(DIM * QKV_N + 255) / 256, 256>>>(qkv_w, w1h, DIM, QKV_N);
    transpose_h_kernel<<<(DIM * DIM + 255) / 256, 256>>>(proj_w, w2h, DIM, DIM);
    bias_expand_kernel<<<(NH * NTOK * NTOK + 255) / 256, 256>>>(rpb, bias_buf);

    // 1) QKV GEMM (fp16)
    gemm_h<<<dim3(QKV_N / 128, MTOK / 128), 256, GEMM_SMEM_H>>>(
        xh, w1h, qkv_b, qkvh, QKV_N);

    // 2) Fused attention + projection (fp32 out)
    attn_proj_fused<<<BATCH, 512, FUSE_SMEM>>>(
        qkvh, mask, bias_buf, w2h, proj_b, out);
}

// round 7
// speedup vs baseline: 3.3105x; 1.0716x over previous
#include <cuda_runtime.h>
#include <cuda_fp16.h>
#include <cstdint>

// Problem constants
#define BATCH   4096
#define NTOK    49
#define DIM     256
#define NH      8
#define HD      32
#define MTOK    (BATCH * NTOK)      // 200704
#define QKV_N   (3 * DIM)           // 768
#define KDIM    256
#define SCALE_F 0.17677669529663687f

// Scratch (device globals)
__device__ __half g_xh[(size_t)MTOK * DIM];     // x in fp16
__device__ __half g_qkvh[(size_t)MTOK * QKV_N]; // qkv in fp16 (308 MB)
__device__ __half g_w1h[QKV_N * DIM];           // qkv_w^T fp16 [768][256]
__device__ __half g_w2h[DIM * DIM];             // proj_w^T fp16 [256][256]
__device__ float  g_bias[NH * NTOK * NTOK];     // expanded rpb [h][i][j]

// fp16 m16n8k16 mma, fp32 accumulate
__device__ __forceinline__ void mma_f16(float c[4], uint32_t a0, uint32_t a1,
                                        uint32_t a2, uint32_t a3,
                                        uint32_t b0, uint32_t b1) {
    asm volatile(
        "mma.sync.aligned.m16n8k16.row.col.f32.f16.f16.f32 "
        "{%0,%1,%2,%3},{%4,%5,%6,%7},{%8,%9},{%0,%1,%2,%3};"
        : "+f"(c[0]), "+f"(c[1]), "+f"(c[2]), "+f"(c[3])
        : "r"(a0), "r"(a1), "r"(a2), "r"(a3), "r"(b0), "r"(b1));
}

__device__ __forceinline__ void cp_async16(void* smem_dst, const void* gptr) {
    uint32_t s = (uint32_t)__cvta_generic_to_shared(smem_dst);
    asm volatile("cp.async.cg.shared.global [%0], [%1], 16;\n" :: "r"(s), "l"(gptr));
}
#define CP_COMMIT()  asm volatile("cp.async.commit_group;\n" ::: "memory")
#define CP_WAIT(n)   asm volatile("cp.async.wait_group %0;\n" :: "n"(n) : "memory")

__device__ __forceinline__ uint32_t pack_h2(float a, float b) {
    __half2 h = __floats2half2_rn(a, b);
    return *(uint32_t*)&h;
}

// ldmatrix x4 transposed (b16): returns 4 transposed 8x8 tile fragments
__device__ __forceinline__ void ldsm_x4_trans(uint32_t& r0, uint32_t& r1,
                                              uint32_t& r2, uint32_t& r3,
                                              uint32_t saddr) {
    asm volatile(
        "ldmatrix.sync.aligned.m8n8.x4.trans.shared.b16 {%0,%1,%2,%3}, [%4];"
        : "=r"(r0), "=r"(r1), "=r"(r2), "=r"(r3) : "r"(saddr));
}

// ---------------------------------------------------------------------------
// Pre-passes
// ---------------------------------------------------------------------------
__global__ void f2h_kernel(const float* __restrict__ in, __half* __restrict__ out,
                           int n4) {
    int i = blockIdx.x * 256 + threadIdx.x;
    if (i < n4) {
        float4 v = ((const float4*)in)[i];
        __half2* o = (__half2*)out;
        o[2 * i]     = __floats2half2_rn(v.x, v.y);
        o[2 * i + 1] = __floats2half2_rn(v.z, v.w);
    }
}

// Merged: w1 transpose, w2 transpose, bias expansion
#define PREP_N1 (DIM * QKV_N)           // 196608
#define PREP_N2 (DIM * DIM)             // 65536
#define PREP_N3 (NH * NTOK * NTOK)      // 19208
#define PREP_TOTAL (PREP_N1 + PREP_N2 + PREP_N3)

__global__ void prep_kernel(const float* __restrict__ qkv_w,
                            const float* __restrict__ proj_w,
                            const float* __restrict__ rpb,
                            __half* __restrict__ w1h, __half* __restrict__ w2h,
                            float* __restrict__ bias) {
    int idx = blockIdx.x * 256 + threadIdx.x;
    if (idx < PREP_N1) {
        int r = idx / QKV_N, c = idx - r * QKV_N;
        w1h[c * DIM + r] = __float2half_rn(qkv_w[idx]);
    } else if (idx < PREP_N1 + PREP_N2) {
        int t = idx - PREP_N1;
        int r = t / DIM, c = t - r * DIM;
        w2h[c * DIM + r] = __float2half_rn(proj_w[t]);
    } else if (idx < PREP_TOTAL) {
        int t = idx - PREP_N1 - PREP_N2;
        int h = t / (NTOK * NTOK), r = t % (NTOK * NTOK);
        int i = r / NTOK, j = r % NTOK;
        int ri = i / 7, ci = i - ri * 7;
        int rj = j / 7, cj = j - rj * 7;
        int ridx = (ri - rj + 6) * 13 + (ci - cj + 6);
        bias[t] = rpb[ridx * NH + h];
    }
}

// ---------------------------------------------------------------------------
// FP16 QKV GEMM (validated, unchanged)
// ---------------------------------------------------------------------------
#define BKH 32
#define TILE_BYTES (128 * 64)
#define STAGE_BYTES (2 * TILE_BYTES)
#define HSTAGES 4
#define GEMM_SMEM_H (HSTAGES * STAGE_BYTES)

__global__ __launch_bounds__(256, 2) void gemm_h(
    const __half* __restrict__ A, const __half* __restrict__ BT,
    const float* __restrict__ bias, __half* __restrict__ C, int N)
{
    extern __shared__ __align__(128) char smem[];

    const int tid  = threadIdx.x;
    const int lane = tid & 31;
    const int warp = tid >> 5;
    const int wm   = warp & 1;
    const int wn   = warp >> 1;
    const int bm   = blockIdx.y * 128;
    const int bn   = blockIdx.x * 128;
    const int tig  = lane & 3;
    const int grp  = lane >> 2;

    float c[4][4][4];
    #pragma unroll
    for (int mi = 0; mi < 4; mi++)
        #pragma unroll
        for (int ni = 0; ni < 4; ni++)
            #pragma unroll
            for (int r = 0; r < 4; r++) c[mi][ni][r] = 0.f;

    auto load_stage = [&](int slot, int kt) {
        char* ab = smem + slot * STAGE_BYTES;
        char* bb = ab + TILE_BYTES;
        const __half* ag = A  + (size_t)bm * KDIM + kt * BKH;
        const __half* bg = BT + (size_t)bn * KDIM + kt * BKH;
        #pragma unroll
        for (int j = 0; j < 2; j++) {
            int sgi = tid + j * 256;
            int r   = sgi >> 2;
            int cc  = sgi & 3;
            cp_async16(ab + r * 64 + cc * 16, ag + (size_t)r * KDIM + cc * 8);
            cp_async16(bb + r * 64 + cc * 16, bg + (size_t)r * KDIM + cc * 8);
        }
    };

    const int ITERS = KDIM / BKH;
    #pragma unroll
    for (int p = 0; p < HSTAGES - 1; p++) { load_stage(p, p); CP_COMMIT(); }

    for (int it = 0; it < ITERS; it++) {
        CP_WAIT(HSTAGES - 2);
        __syncthreads();

        int nk = it + HSTAGES - 1;
        if (nk < ITERS) load_stage(nk & (HSTAGES - 1), nk);
        CP_COMMIT();

        const char* as = smem + (it & (HSTAGES - 1)) * STAGE_BYTES;
        const char* bs = as + TILE_BYTES;

        uint4 ra[4], rb[4];
        #pragma unroll
        for (int mi = 0; mi < 4; mi++) {
            int row = wm * 64 + mi * 16 + grp;
            ra[mi] = *(const uint4*)(as + row * 64 + tig * 16);
            rb[mi] = *(const uint4*)(as + (row + 8) * 64 + tig * 16);
        }
        #pragma unroll
        for (int ni = 0; ni < 4; ni++) {
            int col = wn * 32 + ni * 8 + grp;
            uint4 sb = *(const uint4*)(bs + col * 64 + tig * 16);
            #pragma unroll
            for (int mi = 0; mi < 4; mi++) {
                mma_f16(c[mi][ni], ra[mi].x, rb[mi].x, ra[mi].y, rb[mi].y, sb.x, sb.y);
                mma_f16(c[mi][ni], ra[mi].z, rb[mi].z, ra[mi].w, rb[mi].w, sb.z, sb.w);
            }
        }
    }

    #pragma unroll
    for (int mi = 0; mi < 4; mi++) {
        int row0 = bm + wm * 64 + mi * 16 + grp;
        #pragma unroll
        for (int ni = 0; ni < 4; ni++) {
            int col0 = bn + wn * 32 + ni * 8 + tig * 2;
            float bi0 = bias[col0], bi1 = bias[col0 + 1];
            *(__half2*)(C + (size_t)row0 * N + col0) =
                __floats2half2_rn(c[mi][ni][0] + bi0, c[mi][ni][1] + bi1);
            *(__half2*)(C + (size_t)(row0 + 8) * N + col0) =
                __floats2half2_rn(c[mi][ni][2] + bi0, c[mi][ni][3] + bi1);
        }
    }
}

// ---------------------------------------------------------------------------
// Fused attention + projection v2: one block per window, 512 threads.
// RAW has 64 padded rows (49 real, 15 zeroed). PV B-fragments come straight
// from natural-layout V via ldmatrix.x4.trans (no transpose buffer).
// AO is a separate region (no aliasing).
// ---------------------------------------------------------------------------
#define RAW_STRIDE 1552                 // bytes per qkv row (768 halves + 8 pad)
#define RAW_ROWS   64
#define RAW_BYTES  (RAW_ROWS * RAW_STRIDE)   // 99328
#define AO_OFF     RAW_BYTES
#define AO_STRIDE  576                  // bytes per attn-out row (288 halves)
#define AO_BYTES   (64 * AO_STRIDE)     // 36864
#define FUSE_SMEM  (AO_OFF + AO_BYTES)  // 136192

__global__ __launch_bounds__(512, 1) void attn_proj_fused(
    const __half* __restrict__ qkv, const float* __restrict__ mask,
    const float* __restrict__ bias, const __half* __restrict__ w2,
    const float* __restrict__ proj_b, float* __restrict__ out)
{
    extern __shared__ __align__(128) char sm[];
    const uint32_t sbase = (uint32_t)__cvta_generic_to_shared(sm);

    const int b    = blockIdx.x;
    const int tid  = threadIdx.x;
    const int lane = tid & 31;
    const int wid  = tid >> 5;
    const int g    = lane >> 2;     // 0..7
    const int q    = lane & 3;      // 0..3

    // ---- Phase 1: async load window qkv rows 0..48
    {
        const __half* src = qkv + (size_t)b * NTOK * QKV_N;
        for (int idx = tid; idx < NTOK * 96; idx += 512) {
            int tok = idx / 96, c16 = idx - tok * 96;
            cp_async16(sm + tok * RAW_STRIDE + c16 * 16,
                       src + (size_t)tok * QKV_N + c16 * 8);
        }
        CP_COMMIT();
    }
    // Zero pad rows 49..63 while loads fly (15 rows * 388 words)
    for (int idx = tid; idx < 15 * 388; idx += 512) {
        int r = idx / 388, w = idx - r * 388;
        *(uint32_t*)(sm + (NTOK + r) * RAW_STRIDE + w * 4) = 0;
    }
    CP_WAIT(0);
    __syncthreads();

    // ---- Phase 2: S = Q*K^T per warp (head h, rows [sub*32, sub*32+32))
    const int h   = wid >> 1;
    const int sub = wid & 1;
    const int hoff = h * 64;            // head byte offset within q/k segment

    float c[2][7][4];
    #pragma unroll
    for (int mi = 0; mi < 2; mi++)
        #pragma unroll
        for (int nt = 0; nt < 7; nt++)
            #pragma unroll
            for (int r = 0; r < 4; r++) c[mi][nt][r] = 0.f;

    uint32_t af[2][2][4];
    #pragma unroll
    for (int mi = 0; mi < 2; mi++) {
        int r0 = sub * 32 + mi * 16 + g;
        #pragma unroll
        for (int cc = 0; cc < 2; cc++) {
            const char* base = sm + hoff + cc * 32 + q * 4;
            af[mi][cc][0] = *(const uint32_t*)(base + r0 * RAW_STRIDE);
            af[mi][cc][1] = *(const uint32_t*)(base + (r0 + 8) * RAW_STRIDE);
            af[mi][cc][2] = *(const uint32_t*)(base + r0 * RAW_STRIDE + 16);
            af[mi][cc][3] = *(const uint32_t*)(base + (r0 + 8) * RAW_STRIDE + 16);
        }
    }
    #pragma unroll
    for (int nt = 0; nt < 7; nt++) {
        int j = nt * 8 + g;
        #pragma unroll
        for (int cc = 0; cc < 2; cc++) {
            const char* base = sm + j * RAW_STRIDE + 512 + hoff + cc * 32 + q * 4;
            uint32_t b0 = *(const uint32_t*)(base);
            uint32_t b1 = *(const uint32_t*)(base + 16);
            #pragma unroll
            for (int mi = 0; mi < 2; mi++)
                mma_f16(c[mi][nt], af[mi][cc][0], af[mi][cc][1],
                        af[mi][cc][2], af[mi][cc][3], b0, b1);
        }
    }

    // ---- Phase 3: scale + bias + mask + register softmax
    const float* mrow = mask + (size_t)b * NTOK * NTOK;
    const float* brow = bias + h * NTOK * NTOK;
    float inv0[2], inv1[2];
    #pragma unroll
    for (int mi = 0; mi < 2; mi++) {
        int i0 = sub * 32 + mi * 16 + g;
        int i1 = i0 + 8;
        bool vi0 = i0 < NTOK, vi1 = i1 < NTOK;
        #pragma unroll
        for (int nt = 0; nt < 7; nt++) {
            int j0 = nt * 8 + 2 * q, j1 = j0 + 1;
            bool vj0 = j0 < NTOK, vj1 = j1 < NTOK;
            c[mi][nt][0] = (vi0 && vj0) ? c[mi][nt][0] * SCALE_F + brow[i0 * NTOK + j0] + mrow[i0 * NTOK + j0] : -1e30f;
            c[mi][nt][1] = (vi0 && vj1) ? c[mi][nt][1] * SCALE_F + brow[i0 * NTOK + j1] + mrow[i0 * NTOK + j1] : -1e30f;
            c[mi][nt][2] = (vi1 && vj0) ? c[mi][nt][2] * SCALE_F + brow[i1 * NTOK + j0] + mrow[i1 * NTOK + j0] : -1e30f;
            c[mi][nt][3] = (vi1 && vj1) ? c[mi][nt][3] * SCALE_F + brow[i1 * NTOK + j1] + mrow[i1 * NTOK + j1] : -1e30f;
        }
        float m0 = -1e30f, m1 = -1e30f;
        #pragma unroll
        for (int nt = 0; nt < 7; nt++) {
            m0 = fmaxf(m0, fmaxf(c[mi][nt][0], c[mi][nt][1]));
            m1 = fmaxf(m1, fmaxf(c[mi][nt][2], c[mi][nt][3]));
        }
        m0 = fmaxf(m0, __shfl_xor_sync(0xffffffffu, m0, 1));
        m0 = fmaxf(m0, __shfl_xor_sync(0xffffffffu, m0, 2));
        m1 = fmaxf(m1, __shfl_xor_sync(0xffffffffu, m1, 1));
        m1 = fmaxf(m1, __shfl_xor_sync(0xffffffffu, m1, 2));
        float s0 = 0.f, s1 = 0.f;
        #pragma unroll
        for (int nt = 0; nt < 7; nt++) {
            c[mi][nt][0] = __expf(c[mi][nt][0] - m0); s0 += c[mi][nt][0];
            c[mi][nt][1] = __expf(c[mi][nt][1] - m0); s0 += c[mi][nt][1];
            c[mi][nt][2] = __expf(c[mi][nt][2] - m1); s1 += c[mi][nt][2];
            c[mi][nt][3] = __expf(c[mi][nt][3] - m1); s1 += c[mi][nt][3];
        }
        s0 += __shfl_xor_sync(0xffffffffu, s0, 1);
        s0 += __shfl_xor_sync(0xffffffffu, s0, 2);
        s1 += __shfl_xor_sync(0xffffffffu, s1, 1);
        s1 += __shfl_xor_sync(0xffffffffu, s1, 2);
        inv0[mi] = 1.f / s0;
        inv1[mi] = 1.f / s1;
    }

    // ---- Pack P into fp16 A-fragments (registers only)
    uint32_t pa[2][4][4];
    #pragma unroll
    for (int mi = 0; mi < 2; mi++) {
        #pragma unroll
        for (int ch = 0; ch < 4; ch++) {
            int nt0 = 2 * ch, nt1 = 2 * ch + 1;
            pa[mi][ch][0] = pack_h2(c[mi][nt0][0] * inv0[mi], c[mi][nt0][1] * inv0[mi]);
            pa[mi][ch][1] = pack_h2(c[mi][nt0][2] * inv1[mi], c[mi][nt0][3] * inv1[mi]);
            if (nt1 < 7) {
                pa[mi][ch][2] = pack_h2(c[mi][nt1][0] * inv0[mi], c[mi][nt1][1] * inv0[mi]);
                pa[mi][ch][3] = pack_h2(c[mi][nt1][2] * inv1[mi], c[mi][nt1][3] * inv1[mi]);
            } else {
                pa[mi][ch][2] = 0u;
                pa[mi][ch][3] = 0u;
            }
        }
    }

    // ---- Phase 4: PV mma with ldmatrix.trans B-frags from natural V rows
    // V segment of row j lives at j*RAW_STRIDE + 1024 (+ h*64 head offset)
    #pragma unroll
    for (int mi = 0; mi < 2; mi++) {
        int i0 = sub * 32 + mi * 16 + g;
        int i1 = i0 + 8;
        #pragma unroll
        for (int ni = 0; ni < 4; ni++) {
            float o[4] = {0.f, 0.f, 0.f, 0.f};
            #pragma unroll
            for (int hf = 0; hf < 2; hf++) {
                // tiles: j = hf*32 + lane  (4 stacked 8-row tiles)
                uint32_t addr = sbase + (uint32_t)(hf * 32 + lane) * RAW_STRIDE
                              + 1024 + hoff + ni * 16;
                uint32_t r0, r1, r2, r3;
                ldsm_x4_trans(r0, r1, r2, r3, addr);
                mma_f16(o, pa[mi][2 * hf][0], pa[mi][2 * hf][1],
                        pa[mi][2 * hf][2], pa[mi][2 * hf][3], r0, r1);
                mma_f16(o, pa[mi][2 * hf + 1][0], pa[mi][2 * hf + 1][1],
                        pa[mi][2 * hf + 1][2], pa[mi][2 * hf + 1][3], r2, r3);
            }
            int colb = (h * 32 + ni * 8) * 2 + q * 4;
            *(uint32_t*)(sm + AO_OFF + i0 * AO_STRIDE + colb) = pack_h2(o[0], o[1]);
            *(uint32_t*)(sm + AO_OFF + i1 * AO_STRIDE + colb) = pack_h2(o[2], o[3]);
        }
    }
    __syncthreads();

    // ---- Phase 5: proj GEMM [64x256] = AO[64x256] x W2T[256x256]^T
    const int wm = wid & 1;
    const int wn = wid >> 1;           // 0..7
    float d[2][4][4];
    #pragma unroll
    for (int mi = 0; mi < 2; mi++)
        #pragma unroll
        for (int ni = 0; ni < 4; ni++)
            #pragma unroll
            for (int r = 0; r < 4; r++) d[mi][ni][r] = 0.f;

    #pragma unroll
    for (int cp = 0; cp < 8; cp++) {
        uint4 ra[2], rb[2];
        #pragma unroll
        for (int mi = 0; mi < 2; mi++) {
            int r0 = wm * 32 + mi * 16 + g;
            ra[mi] = *(const uint4*)(sm + AO_OFF + r0 * AO_STRIDE + cp * 64 + q * 16);
            rb[mi] = *(const uint4*)(sm + AO_OFF + (r0 + 8) * AO_STRIDE + cp * 64 + q * 16);
        }
        #pragma unroll
        for (int ni = 0; ni < 4; ni++) {
            int n = wn * 32 + ni * 8 + g;
            uint4 sb = *(const uint4*)(w2 + (size_t)n * KDIM + cp * 32 + q * 8);
            #pragma unroll
            for (int mi = 0; mi < 2; mi++) {
                mma_f16(d[mi][ni], ra[mi].x, rb[mi].x, ra[mi].y, rb[mi].y, sb.x, sb.y);
                mma_f16(d[mi][ni], ra[mi].z, rb[mi].z, ra[mi].w, rb[mi].w, sb.z, sb.w);
            }
        }
    }

    // ---- Epilogue: + proj_b, fp32 out (valid rows only)
    #pragma unroll
    for (int mi = 0; mi < 2; mi++) {
        int i0 = wm * 32 + mi * 16 + g;
        int i1 = i0 + 8;
        #pragma unroll
        for (int ni = 0; ni < 4; ni++) {
            int n0 = wn * 32 + ni * 8 + 2 * q;
            float2 pb = *(const float2*)(proj_b + n0);
            if (i0 < NTOK) {
                float2 v = make_float2(d[mi][ni][0] + pb.x, d[mi][ni][1] + pb.y);
                *(float2*)(out + ((size_t)b * NTOK + i0) * DIM + n0) = v;
            }
            if (i1 < NTOK) {
                float2 v = make_float2(d[mi][ni][2] + pb.x, d[mi][ni][3] + pb.y);
                *(float2*)(out + ((size_t)b * NTOK + i1) * DIM + n0) = v;
            }
        }
    }
}

// ---------------------------------------------------------------------------
extern "C" void kernel_launch(void* const* d_in, const int* in_sizes, int n_in,
                              void* d_out, int out_size)
{
    const float* x      = (const float*)d_in[0];
    const float* mask   = (const float*)d_in[1];
    const float* qkv_w  = (const float*)d_in[2];
    const float* qkv_b  = (const float*)d_in[3];
    const float* rpb    = (const float*)d_in[4];
    const float* proj_w = (const float*)d_in[5];
    const float* proj_b = (const float*)d_in[6];
    float* out = (float*)d_out;

    __half *xh, *qkvh, *w1h, *w2h;
    float *bias_buf;
    cudaGetSymbolAddress((void**)&xh, g_xh);
    cudaGetSymbolAddress((void**)&qkvh, g_qkvh);
    cudaGetSymbolAddress((void**)&w1h, g_w1h);
    cudaGetSymbolAddress((void**)&w2h, g_w2h);
    cudaGetSymbolAddress((void**)&bias_buf, g_bias);

    cudaFuncSetAttribute(gemm_h,
                         cudaFuncAttributeMaxDynamicSharedMemorySize, GEMM_SMEM_H);
    cudaFuncSetAttribute(attn_proj_fused,
                         cudaFuncAttributeMaxDynamicSharedMemorySize, FUSE_SMEM);

    // 0) Pre-passes
    int n4 = MTOK * DIM / 4;
    f2h_kernel<<<(n4 + 255) / 256, 256>>>(x, xh, n4);
    prep_kernel<<<(PREP_TOTAL + 255) / 256, 256>>>(qkv_w, proj_w, rpb,
                                                   w1h, w2h, bias_buf);

    // 1) QKV GEMM (fp16)
    gemm_h<<<dim3(QKV_N / 128, MTOK / 128), 256, GEMM_SMEM_H>>>(
        xh, w1h, qkv_b, qkvh, QKV_N);

    // 2) Fused attention + projection (fp32 out)
    attn_proj_fused<<<BATCH, 512, FUSE_SMEM>>>(
        qkvh, mask, bias_buf, w2h, proj_b, out);
}

// round 8
// speedup vs baseline: 3.5077x; 1.0596x over previous
#include <cuda_runtime.h>
#include <cuda_fp16.h>
#include <cstdint>

// Problem constants
#define BATCH   4096
#define NTOK    49
#define DIM     256
#define NH      8
#define HD      32
#define MTOK    (BATCH * NTOK)      // 200704
#define QKV_N   (3 * DIM)           // 768
#define KDIM    256
#define SCALE_F 0.17677669529663687f

// Scratch (device globals)
__device__ __half g_xh[(size_t)MTOK * DIM];     // x in fp16
__device__ __half g_qkvh[(size_t)MTOK * QKV_N]; // qkv in fp16 (308 MB)
__device__ __half g_w1h[QKV_N * DIM];           // qkv_w^T fp16 [768][256]
__device__ __half g_w2h[DIM * DIM];             // proj_w^T fp16 [256][256]
__device__ __half g_biash[NH * NTOK * NTOK];    // expanded rpb fp16 [h][i][j]

// fp16 m16n8k16 mma, fp32 accumulate
__device__ __forceinline__ void mma_f16(float c[4], uint32_t a0, uint32_t a1,
                                        uint32_t a2, uint32_t a3,
                                        uint32_t b0, uint32_t b1) {
    asm volatile(
        "mma.sync.aligned.m16n8k16.row.col.f32.f16.f16.f32 "
        "{%0,%1,%2,%3},{%4,%5,%6,%7},{%8,%9},{%0,%1,%2,%3};"
        : "+f"(c[0]), "+f"(c[1]), "+f"(c[2]), "+f"(c[3])
        : "r"(a0), "r"(a1), "r"(a2), "r"(a3), "r"(b0), "r"(b1));
}

__device__ __forceinline__ void cp_async16(void* smem_dst, const void* gptr) {
    uint32_t s = (uint32_t)__cvta_generic_to_shared(smem_dst);
    asm volatile("cp.async.cg.shared.global [%0], [%1], 16;\n" :: "r"(s), "l"(gptr));
}
__device__ __forceinline__ void cp_async4(void* smem_dst, const void* gptr) {
    uint32_t s = (uint32_t)__cvta_generic_to_shared(smem_dst);
    asm volatile("cp.async.ca.shared.global [%0], [%1], 4;\n" :: "r"(s), "l"(gptr));
}
#define CP_COMMIT()  asm volatile("cp.async.commit_group;\n" ::: "memory")
#define CP_WAIT(n)   asm volatile("cp.async.wait_group %0;\n" :: "n"(n) : "memory")

__device__ __forceinline__ uint32_t pack_h2(float a, float b) {
    __half2 h = __floats2half2_rn(a, b);
    return *(uint32_t*)&h;
}

__device__ __forceinline__ void ldsm_x4(uint32_t& r0, uint32_t& r1,
                                        uint32_t& r2, uint32_t& r3,
                                        uint32_t saddr) {
    asm volatile(
        "ldmatrix.sync.aligned.m8n8.x4.shared.b16 {%0,%1,%2,%3}, [%4];"
        : "=r"(r0), "=r"(r1), "=r"(r2), "=r"(r3) : "r"(saddr));
}
__device__ __forceinline__ void ldsm_x4_trans(uint32_t& r0, uint32_t& r1,
                                              uint32_t& r2, uint32_t& r3,
                                              uint32_t saddr) {
    asm volatile(
        "ldmatrix.sync.aligned.m8n8.x4.trans.shared.b16 {%0,%1,%2,%3}, [%4];"
        : "=r"(r0), "=r"(r1), "=r"(r2), "=r"(r3) : "r"(saddr));
}

// ---------------------------------------------------------------------------
// Pre-passes
// ---------------------------------------------------------------------------
__global__ void f2h_kernel(const float* __restrict__ in, __half* __restrict__ out,
                           int n4) {
    int i = blockIdx.x * 256 + threadIdx.x;
    if (i < n4) {
        float4 v = ((const float4*)in)[i];
        __half2* o = (__half2*)out;
        o[2 * i]     = __floats2half2_rn(v.x, v.y);
        o[2 * i + 1] = __floats2half2_rn(v.z, v.w);
    }
}

#define PREP_N1 (DIM * QKV_N)           // 196608
#define PREP_N2 (DIM * DIM)             // 65536
#define PREP_N3 (NH * NTOK * NTOK)      // 19208
#define PREP_TOTAL (PREP_N1 + PREP_N2 + PREP_N3)

__global__ void prep_kernel(const float* __restrict__ qkv_w,
                            const float* __restrict__ proj_w,
                            const float* __restrict__ rpb,
                            __half* __restrict__ w1h, __half* __restrict__ w2h,
                            __half* __restrict__ biash) {
    int idx = blockIdx.x * 256 + threadIdx.x;
    if (idx < PREP_N1) {
        int r = idx / QKV_N, c = idx - r * QKV_N;
        w1h[c * DIM + r] = __float2half_rn(qkv_w[idx]);
    } else if (idx < PREP_N1 + PREP_N2) {
        int t = idx - PREP_N1;
        int r = t / DIM, c = t - r * DIM;
        w2h[c * DIM + r] = __float2half_rn(proj_w[t]);
    } else if (idx < PREP_TOTAL) {
        int t = idx - PREP_N1 - PREP_N2;
        int h = t / (NTOK * NTOK), r = t % (NTOK * NTOK);
        int i = r / NTOK, j = r % NTOK;
        int ri = i / 7, ci = i - ri * 7;
        int rj = j / 7, cj = j - rj * 7;
        int ridx = (ri - rj + 6) * 13 + (ci - cj + 6);
        biash[t] = __float2half_rn(rpb[ridx * NH + h]);
    }
}

// ---------------------------------------------------------------------------
// FP16 QKV GEMM (validated, unchanged)
// ---------------------------------------------------------------------------
#define BKH 32
#define TILE_BYTES (128 * 64)
#define STAGE_BYTES (2 * TILE_BYTES)
#define HSTAGES 4
#define GEMM_SMEM_H (HSTAGES * STAGE_BYTES)

__global__ __launch_bounds__(256, 2) void gemm_h(
    const __half* __restrict__ A, const __half* __restrict__ BT,
    const float* __restrict__ bias, __half* __restrict__ C, int N)
{
    extern __shared__ __align__(128) char smem[];

    const int tid  = threadIdx.x;
    const int lane = tid & 31;
    const int warp = tid >> 5;
    const int wm   = warp & 1;
    const int wn   = warp >> 1;
    const int bm   = blockIdx.y * 128;
    const int bn   = blockIdx.x * 128;
    const int tig  = lane & 3;
    const int grp  = lane >> 2;

    float c[4][4][4];
    #pragma unroll
    for (int mi = 0; mi < 4; mi++)
        #pragma unroll
        for (int ni = 0; ni < 4; ni++)
            #pragma unroll
            for (int r = 0; r < 4; r++) c[mi][ni][r] = 0.f;

    auto load_stage = [&](int slot, int kt) {
        char* ab = smem + slot * STAGE_BYTES;
        char* bb = ab + TILE_BYTES;
        const __half* ag = A  + (size_t)bm * KDIM + kt * BKH;
        const __half* bg = BT + (size_t)bn * KDIM + kt * BKH;
        #pragma unroll
        for (int j = 0; j < 2; j++) {
            int sgi = tid + j * 256;
            int r   = sgi >> 2;
            int cc  = sgi & 3;
            cp_async16(ab + r * 64 + cc * 16, ag + (size_t)r * KDIM + cc * 8);
            cp_async16(bb + r * 64 + cc * 16, bg + (size_t)r * KDIM + cc * 8);
        }
    };

    const int ITERS = KDIM / BKH;
    #pragma unroll
    for (int p = 0; p < HSTAGES - 1; p++) { load_stage(p, p); CP_COMMIT(); }

    for (int it = 0; it < ITERS; it++) {
        CP_WAIT(HSTAGES - 2);
        __syncthreads();

        int nk = it + HSTAGES - 1;
        if (nk < ITERS) load_stage(nk & (HSTAGES - 1), nk);
        CP_COMMIT();

        const char* as = smem + (it & (HSTAGES - 1)) * STAGE_BYTES;
        const char* bs = as + TILE_BYTES;

        uint4 ra[4], rb[4];
        #pragma unroll
        for (int mi = 0; mi < 4; mi++) {
            int row = wm * 64 + mi * 16 + grp;
            ra[mi] = *(const uint4*)(as + row * 64 + tig * 16);
            rb[mi] = *(const uint4*)(as + (row + 8) * 64 + tig * 16);
        }
        #pragma unroll
        for (int ni = 0; ni < 4; ni++) {
            int col = wn * 32 + ni * 8 + grp;
            uint4 sb = *(const uint4*)(bs + col * 64 + tig * 16);
            #pragma unroll
            for (int mi = 0; mi < 4; mi++) {
                mma_f16(c[mi][ni], ra[mi].x, rb[mi].x, ra[mi].y, rb[mi].y, sb.x, sb.y);
                mma_f16(c[mi][ni], ra[mi].z, rb[mi].z, ra[mi].w, rb[mi].w, sb.z, sb.w);
            }
        }
    }

    #pragma unroll
    for (int mi = 0; mi < 4; mi++) {
        int row0 = bm + wm * 64 + mi * 16 + grp;
        #pragma unroll
        for (int ni = 0; ni < 4; ni++) {
            int col0 = bn + wn * 32 + ni * 8 + tig * 2;
            float bi0 = bias[col0], bi1 = bias[col0 + 1];
            *(__half2*)(C + (size_t)row0 * N + col0) =
                __floats2half2_rn(c[mi][ni][0] + bi0, c[mi][ni][1] + bi1);
            *(__half2*)(C + (size_t)(row0 + 8) * N + col0) =
                __floats2half2_rn(c[mi][ni][2] + bi0, c[mi][ni][3] + bi1);
        }
    }
}

// ---------------------------------------------------------------------------
// Fused attention + projection v3: one block per window, 512 threads.
// Q/K/V in separate 528B-stride regions (odd 16B stride: ldmatrix-safe).
// S-phase operands via ldmatrix.x4; V via ldmatrix.x4.trans (validated).
// Mask (fp32) and bias (fp16) staged to smem via cp.async in phase 1.
// ---------------------------------------------------------------------------
#define QKV_STRIDE 528
#define REG_BYTES  (64 * QKV_STRIDE)    // 33792 per region
#define QOFF   0
#define KOFF   REG_BYTES
#define VOFF   (2 * REG_BYTES)
#define AOOFF  (3 * REG_BYTES)          // 101376
#define AO_STRIDE 576
#define MOFF   (AOOFF + 64 * AO_STRIDE) // 138240
#define BOFF   (MOFF + 9616)            // 147856 (16B aligned)
#define FUSE_SMEM (BOFF + NH * NTOK * NTOK * 2)   // 186272

__global__ __launch_bounds__(512, 1) void attn_proj_fused(
    const __half* __restrict__ qkv, const float* __restrict__ mask,
    const __half* __restrict__ biash, const __half* __restrict__ w2,
    const float* __restrict__ proj_b, float* __restrict__ out)
{
    extern __shared__ __align__(128) char sm[];
    const uint32_t sbase = (uint32_t)__cvta_generic_to_shared(sm);

    const int b    = blockIdx.x;
    const int tid  = threadIdx.x;
    const int lane = tid & 31;
    const int wid  = tid >> 5;
    const int g    = lane >> 2;     // 0..7
    const int q    = lane & 3;      // 0..3

    // ---- Phase 1: async loads (qkv rows, mask, bias table)
    {
        const __half* src = qkv + (size_t)b * NTOK * QKV_N;
        for (int idx = tid; idx < NTOK * 96; idx += 512) {
            int tok = idx / 96, c16 = idx - tok * 96;
            int seg = c16 >> 5;                  // 0=q 1=k 2=v
            int off = (c16 & 31) * 16;
            cp_async16(sm + seg * REG_BYTES + tok * QKV_STRIDE + off,
                       src + (size_t)tok * QKV_N + c16 * 8);
        }
        const float* mrow = mask + (size_t)b * NTOK * NTOK;
        for (int idx = tid; idx < NTOK * NTOK; idx += 512)
            cp_async4(sm + MOFF + idx * 4, mrow + idx);
        for (int idx = tid; idx < (NH * NTOK * NTOK) / 8; idx += 512)
            cp_async16(sm + BOFF + idx * 16, biash + idx * 8);
        CP_COMMIT();
    }
    // Zero pad rows 49..63 of Q/K/V while loads fly
    for (int idx = tid; idx < 3 * 15 * 132; idx += 512) {
        int reg = idx / (15 * 132);
        int rem = idx - reg * (15 * 132);
        int r = rem / 132, w = rem - r * 132;
        *(uint32_t*)(sm + reg * REG_BYTES + (NTOK + r) * QKV_STRIDE + w * 4) = 0;
    }
    CP_WAIT(0);
    __syncthreads();

    // ---- Phase 2: S = Q*K^T per warp (head h, rows [sub*32, sub*32+32))
    const int h   = wid >> 1;
    const int sub = wid & 1;
    const int hoff = h * 64;            // head byte offset within a row

    float c[2][7][4];
    #pragma unroll
    for (int mi = 0; mi < 2; mi++)
        #pragma unroll
        for (int nt = 0; nt < 7; nt++)
            #pragma unroll
            for (int r = 0; r < 4; r++) c[mi][nt][r] = 0.f;

    uint32_t afr[2][2][4];
    #pragma unroll
    for (int mi = 0; mi < 2; mi++) {
        int r0 = sub * 32 + mi * 16;
        #pragma unroll
        for (int cc = 0; cc < 2; cc++) {
            uint32_t addr = sbase + QOFF + (uint32_t)(r0 + (lane & 15)) * QKV_STRIDE
                          + hoff + cc * 32 + ((lane >> 4) * 16);
            ldsm_x4(afr[mi][cc][0], afr[mi][cc][1], afr[mi][cc][2], afr[mi][cc][3], addr);
        }
    }
    #pragma unroll
    for (int nt = 0; nt < 7; nt++) {
        uint32_t kaddr = sbase + KOFF + (uint32_t)(nt * 8 + (lane & 7)) * QKV_STRIDE
                       + hoff + ((lane >> 3) * 16);
        uint32_t b0, b1, b2, b3;
        ldsm_x4(b0, b1, b2, b3, kaddr);
        #pragma unroll
        for (int mi = 0; mi < 2; mi++) {
            mma_f16(c[mi][nt], afr[mi][0][0], afr[mi][0][1],
                    afr[mi][0][2], afr[mi][0][3], b0, b1);
            mma_f16(c[mi][nt], afr[mi][1][0], afr[mi][1][1],
                    afr[mi][1][2], afr[mi][1][3], b2, b3);
        }
    }

    // ---- Phase 3: scale + bias + mask + register softmax (smem sources)
    const float* mrow_s = (const float*)(sm + MOFF);
    const __half* brow_s = (const __half*)(sm + BOFF) + h * NTOK * NTOK;
    float inv0[2], inv1[2];
    #pragma unroll
    for (int mi = 0; mi < 2; mi++) {
        int i0 = sub * 32 + mi * 16 + g;
        int i1 = i0 + 8;
        bool vi0 = i0 < NTOK, vi1 = i1 < NTOK;
        #pragma unroll
        for (int nt = 0; nt < 7; nt++) {
            int j0 = nt * 8 + 2 * q, j1 = j0 + 1;
            bool vj0 = j0 < NTOK, vj1 = j1 < NTOK;
            c[mi][nt][0] = (vi0 && vj0) ? c[mi][nt][0] * SCALE_F
                + __half2float(brow_s[i0 * NTOK + j0]) + mrow_s[i0 * NTOK + j0] : -1e30f;
            c[mi][nt][1] = (vi0 && vj1) ? c[mi][nt][1] * SCALE_F
                + __half2float(brow_s[i0 * NTOK + j1]) + mrow_s[i0 * NTOK + j1] : -1e30f;
            c[mi][nt][2] = (vi1 && vj0) ? c[mi][nt][2] * SCALE_F
                + __half2float(brow_s[i1 * NTOK + j0]) + mrow_s[i1 * NTOK + j0] : -1e30f;
            c[mi][nt][3] = (vi1 && vj1) ? c[mi][nt][3] * SCALE_F
                + __half2float(brow_s[i1 * NTOK + j1]) + mrow_s[i1 * NTOK + j1] : -1e30f;
        }
        float m0 = -1e30f, m1 = -1e30f;
        #pragma unroll
        for (int nt = 0; nt < 7; nt++) {
            m0 = fmaxf(m0, fmaxf(c[mi][nt][0], c[mi][nt][1]));
            m1 = fmaxf(m1, fmaxf(c[mi][nt][2], c[mi][nt][3]));
        }
        m0 = fmaxf(m0, __shfl_xor_sync(0xffffffffu, m0, 1));
        m0 = fmaxf(m0, __shfl_xor_sync(0xffffffffu, m0, 2));
        m1 = fmaxf(m1, __shfl_xor_sync(0xffffffffu, m1, 1));
        m1 = fmaxf(m1, __shfl_xor_sync(0xffffffffu, m1, 2));
        float s0 = 0.f, s1 = 0.f;
        #pragma unroll
        for (int nt = 0; nt < 7; nt++) {
            c[mi][nt][0] = __expf(c[mi][nt][0] - m0); s0 += c[mi][nt][0];
            c[mi][nt][1] = __expf(c[mi][nt][1] - m0); s0 += c[mi][nt][1];
            c[mi][nt][2] = __expf(c[mi][nt][2] - m1); s1 += c[mi][nt][2];
            c[mi][nt][3] = __expf(c[mi][nt][3] - m1); s1 += c[mi][nt][3];
        }
        s0 += __shfl_xor_sync(0xffffffffu, s0, 1);
        s0 += __shfl_xor_sync(0xffffffffu, s0, 2);
        s1 += __shfl_xor_sync(0xffffffffu, s1, 1);
        s1 += __shfl_xor_sync(0xffffffffu, s1, 2);
        inv0[mi] = 1.f / s0;
        inv1[mi] = 1.f / s1;
    }

    // ---- Pack P into fp16 A-fragments (registers only)
    uint32_t pa[2][4][4];
    #pragma unroll
    for (int mi = 0; mi < 2; mi++) {
        #pragma unroll
        for (int ch = 0; ch < 4; ch++) {
            int nt0 = 2 * ch, nt1 = 2 * ch + 1;
            pa[mi][ch][0] = pack_h2(c[mi][nt0][0] * inv0[mi], c[mi][nt0][1] * inv0[mi]);
            pa[mi][ch][1] = pack_h2(c[mi][nt0][2] * inv1[mi], c[mi][nt0][3] * inv1[mi]);
            if (nt1 < 7) {
                pa[mi][ch][2] = pack_h2(c[mi][nt1][0] * inv0[mi], c[mi][nt1][1] * inv0[mi]);
                pa[mi][ch][3] = pack_h2(c[mi][nt1][2] * inv1[mi], c[mi][nt1][3] * inv1[mi]);
            } else {
                pa[mi][ch][2] = 0u;
                pa[mi][ch][3] = 0u;
            }
        }
    }

    // ---- Phase 4: PV mma; B-frags via ldmatrix.trans on V region
    #pragma unroll
    for (int mi = 0; mi < 2; mi++) {
        int i0 = sub * 32 + mi * 16 + g;
        int i1 = i0 + 8;
        #pragma unroll
        for (int ni = 0; ni < 4; ni++) {
            float o[4] = {0.f, 0.f, 0.f, 0.f};
            #pragma unroll
            for (int hf = 0; hf < 2; hf++) {
                uint32_t addr = sbase + VOFF + (uint32_t)(hf * 32 + lane) * QKV_STRIDE
                              + hoff + ni * 16;
                uint32_t r0, r1, r2, r3;
                ldsm_x4_trans(r0, r1, r2, r3, addr);
                mma_f16(o, pa[mi][2 * hf][0], pa[mi][2 * hf][1],
                        pa[mi][2 * hf][2], pa[mi][2 * hf][3], r0, r1);
                mma_f16(o, pa[mi][2 * hf + 1][0], pa[mi][2 * hf + 1][1],
                        pa[mi][2 * hf + 1][2], pa[mi][2 * hf + 1][3], r2, r3);
            }
            int colb = (h * 32 + ni * 8) * 2 + q * 4;
            *(uint32_t*)(sm + AOOFF + i0 * AO_STRIDE + colb) = pack_h2(o[0], o[1]);
            *(uint32_t*)(sm + AOOFF + i1 * AO_STRIDE + colb) = pack_h2(o[2], o[3]);
        }
    }
    __syncthreads();

    // ---- Phase 5: proj GEMM [64x256] = AO[64x256] x W2T[256x256]^T
    const int wm = wid & 1;
    const int wn = wid >> 1;           // 0..7
    float d[2][4][4];
    #pragma unroll
    for (int mi = 0; mi < 2; mi++)
        #pragma unroll
        for (int ni = 0; ni < 4; ni++)
            #pragma unroll
            for (int r = 0; r < 4; r++) d[mi][ni][r] = 0.f;

    #pragma unroll
    for (int cp = 0; cp < 8; cp++) {
        uint4 ra[2], rb[2];
        #pragma unroll
        for (int mi = 0; mi < 2; mi++) {
            int r0 = wm * 32 + mi * 16 + g;
            ra[mi] = *(const uint4*)(sm + AOOFF + r0 * AO_STRIDE + cp * 64 + q * 16);
            rb[mi] = *(const uint4*)(sm + AOOFF + (r0 + 8) * AO_STRIDE + cp * 64 + q * 16);
        }
        #pragma unroll
        for (int ni = 0; ni < 4; ni++) {
            int n = wn * 32 + ni * 8 + g;
            uint4 sb = *(const uint4*)(w2 + (size_t)n * KDIM + cp * 32 + q * 8);
            #pragma unroll
            for (int mi = 0; mi < 2; mi++) {
                mma_f16(d[mi][ni], ra[mi].x, rb[mi].x, ra[mi].y, rb[mi].y, sb.x, sb.y);
                mma_f16(d[mi][ni], ra[mi].z, rb[mi].z, ra[mi].w, rb[mi].w, sb.z, sb.w);
            }
        }
    }

    // ---- Epilogue: + proj_b, fp32 out (valid rows only)
    #pragma unroll
    for (int mi = 0; mi < 2; mi++) {
        int i0 = wm * 32 + mi * 16 + g;
        int i1 = i0 + 8;
        #pragma unroll
        for (int ni = 0; ni < 4; ni++) {
            int n0 = wn * 32 + ni * 8 + 2 * q;
            float2 pb = *(const float2*)(proj_b + n0);
            if (i0 < NTOK) {
                float2 v = make_float2(d[mi][ni][0] + pb.x, d[mi][ni][1] + pb.y);
                *(float2*)(out + ((size_t)b * NTOK + i0) * DIM + n0) = v;
            }
            if (i1 < NTOK) {
                float2 v = make_float2(d[mi][ni][2] + pb.x, d[mi][ni][3] + pb.y);
                *(float2*)(out + ((size_t)b * NTOK + i1) * DIM + n0) = v;
            }
        }
    }
}

// ---------------------------------------------------------------------------
extern "C" void kernel_launch(void* const* d_in, const int* in_sizes, int n_in,
                              void* d_out, int out_size)
{
    const float* x      = (const float*)d_in[0];
    const float* mask   = (const float*)d_in[1];
    const float* qkv_w  = (const float*)d_in[2];
    const float* qkv_b  = (const float*)d_in[3];
    const float* rpb    = (const float*)d_in[4];
    const float* proj_w = (const float*)d_in[5];
    const float* proj_b = (const float*)d_in[6];
    float* out = (float*)d_out;

    __half *xh, *qkvh, *w1h, *w2h, *biash;
    cudaGetSymbolAddress((void**)&xh, g_xh);
    cudaGetSymbolAddress((void**)&qkvh, g_qkvh);
    cudaGetSymbolAddress((void**)&w1h, g_w1h);
    cudaGetSymbolAddress((void**)&w2h, g_w2h);
    cudaGetSymbolAddress((void**)&biash, g_biash);

    cudaFuncSetAttribute(gemm_h,
                         cudaFuncAttributeMaxDynamicSharedMemorySize, GEMM_SMEM_H);
    cudaFuncSetAttribute(attn_proj_fused,
                         cudaFuncAttributeMaxDynamicSharedMemorySize, FUSE_SMEM);

    // 0) Pre-passes
    int n4 = MTOK * DIM / 4;
    f2h_kernel<<<(n4 + 255) / 256, 256>>>(x, xh, n4);
    prep_kernel<<<(PREP_TOTAL + 255) / 256, 256>>>(qkv_w, proj_w, rpb,
                                                   w1h, w2h, biash);

    // 1) QKV GEMM (fp16)
    gemm_h<<<dim3(QKV_N / 128, MTOK / 128), 256, GEMM_SMEM_H>>>(
        xh, w1h, qkv_b, qkvh, QKV_N);

    // 2) Fused attention + projection (fp32 out)
    attn_proj_fused<<<BATCH, 512, FUSE_SMEM>>>(
        qkvh, mask, biash, w2h, proj_b, out);
}

// round 9
// speedup vs baseline: 3.5234x; 1.0045x over previous
#include <cuda_runtime.h>
#include <cuda_fp16.h>
#include <cstdint>

// Problem constants
#define BATCH   4096
#define NTOK    49
#define DIM     256
#define NH      8
#define HD      32
#define MTOK    (BATCH * NTOK)      // 200704
#define QKV_N   (3 * DIM)           // 768
#define KDIM    256
#define SCALE_F 0.17677669529663687f

// Scratch (device globals)
__device__ __half g_xh[(size_t)MTOK * DIM];     // x in fp16
__device__ __half g_qkvh[(size_t)MTOK * QKV_N]; // qkv in fp16 (308 MB)
__device__ __half g_w1h[QKV_N * DIM];           // qkv_w^T fp16 [768][256]
__device__ __half g_w2h[DIM * DIM];             // proj_w^T fp16 [256][256]
__device__ __half g_biash[NH * NTOK * NTOK];    // expanded rpb fp16 [h][i][j]

// fp16 m16n8k16 mma, fp32 accumulate
__device__ __forceinline__ void mma_f16(float c[4], uint32_t a0, uint32_t a1,
                                        uint32_t a2, uint32_t a3,
                                        uint32_t b0, uint32_t b1) {
    asm volatile(
        "mma.sync.aligned.m16n8k16.row.col.f32.f16.f16.f32 "
        "{%0,%1,%2,%3},{%4,%5,%6,%7},{%8,%9},{%0,%1,%2,%3};"
        : "+f"(c[0]), "+f"(c[1]), "+f"(c[2]), "+f"(c[3])
        : "r"(a0), "r"(a1), "r"(a2), "r"(a3), "r"(b0), "r"(b1));
}

__device__ __forceinline__ void cp_async16(void* smem_dst, const void* gptr) {
    uint32_t s = (uint32_t)__cvta_generic_to_shared(smem_dst);
    asm volatile("cp.async.cg.shared.global [%0], [%1], 16;\n" :: "r"(s), "l"(gptr));
}
__device__ __forceinline__ void cp_async4(void* smem_dst, const void* gptr) {
    uint32_t s = (uint32_t)__cvta_generic_to_shared(smem_dst);
    asm volatile("cp.async.ca.shared.global [%0], [%1], 4;\n" :: "r"(s), "l"(gptr));
}
#define CP_COMMIT()  asm volatile("cp.async.commit_group;\n" ::: "memory")
#define CP_WAIT(n)   asm volatile("cp.async.wait_group %0;\n" :: "n"(n) : "memory")

__device__ __forceinline__ uint32_t pack_h2(float a, float b) {
    __half2 h = __floats2half2_rn(a, b);
    return *(uint32_t*)&h;
}

__device__ __forceinline__ void ldsm_x4(uint32_t& r0, uint32_t& r1,
                                        uint32_t& r2, uint32_t& r3,
                                        uint32_t saddr) {
    asm volatile(
        "ldmatrix.sync.aligned.m8n8.x4.shared.b16 {%0,%1,%2,%3}, [%4];"
        : "=r"(r0), "=r"(r1), "=r"(r2), "=r"(r3) : "r"(saddr));
}
__device__ __forceinline__ void ldsm_x4_trans(uint32_t& r0, uint32_t& r1,
                                              uint32_t& r2, uint32_t& r3,
                                              uint32_t saddr) {
    asm volatile(
        "ldmatrix.sync.aligned.m8n8.x4.trans.shared.b16 {%0,%1,%2,%3}, [%4];"
        : "=r"(r0), "=r"(r1), "=r"(r2), "=r"(r3) : "r"(saddr));
}

// ---------------------------------------------------------------------------
// Pre-passes
// ---------------------------------------------------------------------------
__global__ void f2h_kernel(const float* __restrict__ in, __half* __restrict__ out,
                           int n4) {
    int i = blockIdx.x * 256 + threadIdx.x;
    if (i < n4) {
        float4 v = ((const float4*)in)[i];
        __half2* o = (__half2*)out;
        o[2 * i]     = __floats2half2_rn(v.x, v.y);
        o[2 * i + 1] = __floats2half2_rn(v.z, v.w);
    }
}

#define PREP_N1 (DIM * QKV_N)           // 196608
#define PREP_N2 (DIM * DIM)             // 65536
#define PREP_N3 (NH * NTOK * NTOK)      // 19208
#define PREP_TOTAL (PREP_N1 + PREP_N2 + PREP_N3)

__global__ void prep_kernel(const float* __restrict__ qkv_w,
                            const float* __restrict__ proj_w,
                            const float* __restrict__ rpb,
                            __half* __restrict__ w1h, __half* __restrict__ w2h,
                            __half* __restrict__ biash) {
    int idx = blockIdx.x * 256 + threadIdx.x;
    if (idx < PREP_N1) {
        int r = idx / QKV_N, c = idx - r * QKV_N;
        w1h[c * DIM + r] = __float2half_rn(qkv_w[idx]);
    } else if (idx < PREP_N1 + PREP_N2) {
        int t = idx - PREP_N1;
        int r = t / DIM, c = t - r * DIM;
        w2h[c * DIM + r] = __float2half_rn(proj_w[t]);
    } else if (idx < PREP_TOTAL) {
        int t = idx - PREP_N1 - PREP_N2;
        int h = t / (NTOK * NTOK), r = t % (NTOK * NTOK);
        int i = r / NTOK, j = r % NTOK;
        int ri = i / 7, ci = i - ri * 7;
        int rj = j / 7, cj = j - rj * 7;
        int ridx = (ri - rj + 6) * 13 + (ci - cj + 6);
        biash[t] = __float2half_rn(rpb[ridx * NH + h]);
    }
}

// ---------------------------------------------------------------------------
// FP16 QKV GEMM (validated, unchanged)
// ---------------------------------------------------------------------------
#define BKH 32
#define TILE_BYTES (128 * 64)
#define STAGE_BYTES (2 * TILE_BYTES)
#define HSTAGES 4
#define GEMM_SMEM_H (HSTAGES * STAGE_BYTES)

__global__ __launch_bounds__(256, 2) void gemm_h(
    const __half* __restrict__ A, const __half* __restrict__ BT,
    const float* __restrict__ bias, __half* __restrict__ C, int N)
{
    extern __shared__ __align__(128) char smem[];

    const int tid  = threadIdx.x;
    const int lane = tid & 31;
    const int warp = tid >> 5;
    const int wm   = warp & 1;
    const int wn   = warp >> 1;
    const int bm   = blockIdx.y * 128;
    const int bn   = blockIdx.x * 128;
    const int tig  = lane & 3;
    const int grp  = lane >> 2;

    float c[4][4][4];
    #pragma unroll
    for (int mi = 0; mi < 4; mi++)
        #pragma unroll
        for (int ni = 0; ni < 4; ni++)
            #pragma unroll
            for (int r = 0; r < 4; r++) c[mi][ni][r] = 0.f;

    auto load_stage = [&](int slot, int kt) {
        char* ab = smem + slot * STAGE_BYTES;
        char* bb = ab + TILE_BYTES;
        const __half* ag = A  + (size_t)bm * KDIM + kt * BKH;
        const __half* bg = BT + (size_t)bn * KDIM + kt * BKH;
        #pragma unroll
        for (int j = 0; j < 2; j++) {
            int sgi = tid + j * 256;
            int r   = sgi >> 2;
            int cc  = sgi & 3;
            cp_async16(ab + r * 64 + cc * 16, ag + (size_t)r * KDIM + cc * 8);
            cp_async16(bb + r * 64 + cc * 16, bg + (size_t)r * KDIM + cc * 8);
        }
    };

    const int ITERS = KDIM / BKH;
    #pragma unroll
    for (int p = 0; p < HSTAGES - 1; p++) { load_stage(p, p); CP_COMMIT(); }

    for (int it = 0; it < ITERS; it++) {
        CP_WAIT(HSTAGES - 2);
        __syncthreads();

        int nk = it + HSTAGES - 1;
        if (nk < ITERS) load_stage(nk & (HSTAGES - 1), nk);
        CP_COMMIT();

        const char* as = smem + (it & (HSTAGES - 1)) * STAGE_BYTES;
        const char* bs = as + TILE_BYTES;

        uint4 ra[4], rb[4];
        #pragma unroll
        for (int mi = 0; mi < 4; mi++) {
            int row = wm * 64 + mi * 16 + grp;
            ra[mi] = *(const uint4*)(as + row * 64 + tig * 16);
            rb[mi] = *(const uint4*)(as + (row + 8) * 64 + tig * 16);
        }
        #pragma unroll
        for (int ni = 0; ni < 4; ni++) {
            int col = wn * 32 + ni * 8 + grp;
            uint4 sb = *(const uint4*)(bs + col * 64 + tig * 16);
            #pragma unroll
            for (int mi = 0; mi < 4; mi++) {
                mma_f16(c[mi][ni], ra[mi].x, rb[mi].x, ra[mi].y, rb[mi].y, sb.x, sb.y);
                mma_f16(c[mi][ni], ra[mi].z, rb[mi].z, ra[mi].w, rb[mi].w, sb.z, sb.w);
            }
        }
    }

    #pragma unroll
    for (int mi = 0; mi < 4; mi++) {
        int row0 = bm + wm * 64 + mi * 16 + grp;
        #pragma unroll
        for (int ni = 0; ni < 4; ni++) {
            int col0 = bn + wn * 32 + ni * 8 + tig * 2;
            float bi0 = bias[col0], bi1 = bias[col0 + 1];
            *(__half2*)(C + (size_t)row0 * N + col0) =
                __floats2half2_rn(c[mi][ni][0] + bi0, c[mi][ni][1] + bi1);
            *(__half2*)(C + (size_t)(row0 + 8) * N + col0) =
                __floats2half2_rn(c[mi][ni][2] + bi0, c[mi][ni][3] + bi1);
        }
    }
}

// ---------------------------------------------------------------------------
// Fused attention + projection v3: one block per window, 512 threads.
// Q/K/V in separate 528B-stride regions (odd 16B stride: ldmatrix-safe).
// S-phase operands via ldmatrix.x4; V via ldmatrix.x4.trans (validated).
// Mask (fp32) and bias (fp16) staged to smem via cp.async in phase 1.
// ---------------------------------------------------------------------------
#define QKV_STRIDE 528
#define REG_BYTES  (64 * QKV_STRIDE)    // 33792 per region
#define QOFF   0
#define KOFF   REG_BYTES
#define VOFF   (2 * REG_BYTES)
#define AOOFF  (3 * REG_BYTES)          // 101376
#define AO_STRIDE 576
#define MOFF   (AOOFF + 64 * AO_STRIDE) // 138240
#define BOFF   (MOFF + 9616)            // 147856 (16B aligned)
#define FUSE_SMEM (BOFF + NH * NTOK * NTOK * 2)   // 186272

__global__ __launch_bounds__(512, 1) void attn_proj_fused(
    const __half* __restrict__ qkv, const float* __restrict__ mask,
    const __half* __restrict__ biash, const __half* __restrict__ w2,
    const float* __restrict__ proj_b, float* __restrict__ out)
{
    extern __shared__ __align__(128) char sm[];
    const uint32_t sbase = (uint32_t)__cvta_generic_to_shared(sm);

    const int b    = blockIdx.x;
    const int tid  = threadIdx.x;
    const int lane = tid & 31;
    const int wid  = tid >> 5;
    const int g    = lane >> 2;     // 0..7
    const int q    = lane & 3;      // 0..3

    // ---- Phase 1: async loads (qkv rows, mask, bias table)
    {
        const __half* src = qkv + (size_t)b * NTOK * QKV_N;
        for (int idx = tid; idx < NTOK * 96; idx += 512) {
            int tok = idx / 96, c16 = idx - tok * 96;
            int seg = c16 >> 5;                  // 0=q 1=k 2=v
            int off = (c16 & 31) * 16;
            cp_async16(sm + seg * REG_BYTES + tok * QKV_STRIDE + off,
                       src + (size_t)tok * QKV_N + c16 * 8);
        }
        const float* mrow = mask + (size_t)b * NTOK * NTOK;
        for (int idx = tid; idx < NTOK * NTOK; idx += 512)
            cp_async4(sm + MOFF + idx * 4, mrow + idx);
        for (int idx = tid; idx < (NH * NTOK * NTOK) / 8; idx += 512)
            cp_async16(sm + BOFF + idx * 16, biash + idx * 8);
        CP_COMMIT();
    }
    // Zero pad rows 49..63 of Q/K/V while loads fly
    for (int idx = tid; idx < 3 * 15 * 132; idx += 512) {
        int reg = idx / (15 * 132);
        int rem = idx - reg * (15 * 132);
        int r = rem / 132, w = rem - r * 132;
        *(uint32_t*)(sm + reg * REG_BYTES + (NTOK + r) * QKV_STRIDE + w * 4) = 0;
    }
    CP_WAIT(0);
    __syncthreads();

    // ---- Phase 2: S = Q*K^T per warp (head h, rows [sub*32, sub*32+32))
    const int h   = wid >> 1;
    const int sub = wid & 1;
    const int hoff = h * 64;            // head byte offset within a row

    float c[2][7][4];
    #pragma unroll
    for (int mi = 0; mi < 2; mi++)
        #pragma unroll
        for (int nt = 0; nt < 7; nt++)
            #pragma unroll
            for (int r = 0; r < 4; r++) c[mi][nt][r] = 0.f;

    uint32_t afr[2][2][4];
    #pragma unroll
    for (int mi = 0; mi < 2; mi++) {
        int r0 = sub * 32 + mi * 16;
        #pragma unroll
        for (int cc = 0; cc < 2; cc++) {
            uint32_t addr = sbase + QOFF + (uint32_t)(r0 + (lane & 15)) * QKV_STRIDE
                          + hoff + cc * 32 + ((lane >> 4) * 16);
            ldsm_x4(afr[mi][cc][0], afr[mi][cc][1], afr[mi][cc][2], afr[mi][cc][3], addr);
        }
    }
    #pragma unroll
    for (int nt = 0; nt < 7; nt++) {
        uint32_t kaddr = sbase + KOFF + (uint32_t)(nt * 8 + (lane & 7)) * QKV_STRIDE
                       + hoff + ((lane >> 3) * 16);
        uint32_t b0, b1, b2, b3;
        ldsm_x4(b0, b1, b2, b3, kaddr);
        #pragma unroll
        for (int mi = 0; mi < 2; mi++) {
            mma_f16(c[mi][nt], afr[mi][0][0], afr[mi][0][1],
                    afr[mi][0][2], afr[mi][0][3], b0, b1);
            mma_f16(c[mi][nt], afr[mi][1][0], afr[mi][1][1],
                    afr[mi][1][2], afr[mi][1][3], b2, b3);
        }
    }

    // ---- Phase 3: scale + bias + mask + register softmax (smem sources)
    const float* mrow_s = (const float*)(sm + MOFF);
    const __half* brow_s = (const __half*)(sm + BOFF) + h * NTOK * NTOK;
    float inv0[2], inv1[2];
    #pragma unroll
    for (int mi = 0; mi < 2; mi++) {
        int i0 = sub * 32 + mi * 16 + g;
        int i1 = i0 + 8;
        bool vi0 = i0 < NTOK, vi1 = i1 < NTOK;
        #pragma unroll
        for (int nt = 0; nt < 7; nt++) {
            int j0 = nt * 8 + 2 * q, j1 = j0 + 1;
            bool vj0 = j0 < NTOK, vj1 = j1 < NTOK;
            c[mi][nt][0] = (vi0 && vj0) ? c[mi][nt][0] * SCALE_F
                + __half2float(brow_s[i0 * NTOK + j0]) + mrow_s[i0 * NTOK + j0] : -1e30f;
            c[mi][nt][1] = (vi0 && vj1) ? c[mi][nt][1] * SCALE_F
                + __half2float(brow_s[i0 * NTOK + j1]) + mrow_s[i0 * NTOK + j1] : -1e30f;
            c[mi][nt][2] = (vi1 && vj0) ? c[mi][nt][2] * SCALE_F
                + __half2float(brow_s[i1 * NTOK + j0]) + mrow_s[i1 * NTOK + j0] : -1e30f;
            c[mi][nt][3] = (vi1 && vj1) ? c[mi][nt][3] * SCALE_F
                + __half2float(brow_s[i1 * NTOK + j1]) + mrow_s[i1 * NTOK + j1] : -1e30f;
        }
        float m0 = -1e30f, m1 = -1e30f;
        #pragma unroll
        for (int nt = 0; nt < 7; nt++) {
            m0 = fmaxf(m0, fmaxf(c[mi][nt][0], c[mi][nt][1]));
            m1 = fmaxf(m1, fmaxf(c[mi][nt][2], c[mi][nt][3]));
        }
        m0 = fmaxf(m0, __shfl_xor_sync(0xffffffffu, m0, 1));
        m0 = fmaxf(m0, __shfl_xor_sync(0xffffffffu, m0, 2));
        m1 = fmaxf(m1, __shfl_xor_sync(0xffffffffu, m1, 1));
        m1 = fmaxf(m1, __shfl_xor_sync(0xffffffffu, m1, 2));
        float s0 = 0.f, s1 = 0.f;
        #pragma unroll
        for (int nt = 0; nt < 7; nt++) {
            c[mi][nt][0] = __expf(c[mi][nt][0] - m0); s0 += c[mi][nt][0];
            c[mi][nt][1] = __expf(c[mi][nt][1] - m0); s0 += c[mi][nt][1];
            c[mi][nt][2] = __expf(c[mi][nt][2] - m1); s1 += c[mi][nt][2];
            c[mi][nt][3] = __expf(c[mi][nt][3] - m1); s1 += c[mi][nt][3];
        }
        s0 += __shfl_xor_sync(0xffffffffu, s0, 1);
        s0 += __shfl_xor_sync(0xffffffffu, s0, 2);
        s1 += __shfl_xor_sync(0xffffffffu, s1, 1);
        s1 += __shfl_xor_sync(0xffffffffu, s1, 2);
        inv0[mi] = 1.f / s0;
        inv1[mi] = 1.f / s1;
    }

    // ---- Pack P into fp16 A-fragments (registers only)
    uint32_t pa[2][4][4];
    #pragma unroll
    for (int mi = 0; mi < 2; mi++) {
        #pragma unroll
        for (int ch = 0; ch < 4; ch++) {
            int nt0 = 2 * ch, nt1 = 2 * ch + 1;
            pa[mi][ch][0] = pack_h2(c[mi][nt0][0] * inv0[mi], c[mi][nt0][1] * inv0[mi]);
            pa[mi][ch][1] = pack_h2(c[mi][nt0][2] * inv1[mi], c[mi][nt0][3] * inv1[mi]);
            if (nt1 < 7) {
                pa[mi][ch][2] = pack_h2(c[mi][nt1][0] * inv0[mi], c[mi][nt1][1] * inv0[mi]);
                pa[mi][ch][3] = pack_h2(c[mi][nt1][2] * inv1[mi], c[mi][nt1][3] * inv1[mi]);
            } else {
                pa[mi][ch][2] = 0u;
                pa[mi][ch][3] = 0u;
            }
        }
    }

    // ---- Phase 4: PV mma; B-frags via ldmatrix.trans on V region
    #pragma unroll
    for (int mi = 0; mi < 2; mi++) {
        int i0 = sub * 32 + mi * 16 + g;
        int i1 = i0 + 8;
        #pragma unroll
        for (int ni = 0; ni < 4; ni++) {
            float o[4] = {0.f, 0.f, 0.f, 0.f};
            #pragma unroll
            for (int hf = 0; hf < 2; hf++) {
                uint32_t addr = sbase + VOFF + (uint32_t)(hf * 32 + lane) * QKV_STRIDE
                              + hoff + ni * 16;
                uint32_t r0, r1, r2, r3;
                ldsm_x4_trans(r0, r1, r2, r3, addr);
                mma_f16(o, pa[mi][2 * hf][0], pa[mi][2 * hf][1],
                        pa[mi][2 * hf][2], pa[mi][2 * hf][3], r0, r1);
                mma_f16(o, pa[mi][2 * hf + 1][0], pa[mi][2 * hf + 1][1],
                        pa[mi][2 * hf + 1][2], pa[mi][2 * hf + 1][3], r2, r3);
            }
            int colb = (h * 32 + ni * 8) * 2 + q * 4;
            *(uint32_t*)(sm + AOOFF + i0 * AO_STRIDE + colb) = pack_h2(o[0], o[1]);
            *(uint32_t*)(sm + AOOFF + i1 * AO_STRIDE + colb) = pack_h2(o[2], o[3]);
        }
    }
    __syncthreads();

    // ---- Phase 5: proj GEMM [64x256] = AO[64x256] x W2T[256x256]^T
    const int wm = wid & 1;
    const int wn = wid >> 1;           // 0..7
    float d[2][4][4];
    #pragma unroll
    for (int mi = 0; mi < 2; mi++)
        #pragma unroll
        for (int ni = 0; ni < 4; ni++)
            #pragma unroll
            for (int r = 0; r < 4; r++) d[mi][ni][r] = 0.f;

    #pragma unroll
    for (int cp = 0; cp < 8; cp++) {
        uint4 ra[2], rb[2];
        #pragma unroll
        for (int mi = 0; mi < 2; mi++) {
            int r0 = wm * 32 + mi * 16 + g;
            ra[mi] = *(const uint4*)(sm + AOOFF + r0 * AO_STRIDE + cp * 64 + q * 16);
            rb[mi] = *(const uint4*)(sm + AOOFF + (r0 + 8) * AO_STRIDE + cp * 64 + q * 16);
        }
        #pragma unroll
        for (int ni = 0; ni < 4; ni++) {
            int n = wn * 32 + ni * 8 + g;
            uint4 sb = *(const uint4*)(w2 + (size_t)n * KDIM + cp * 32 + q * 8);
            #pragma unroll
            for (int mi = 0; mi < 2; mi++) {
                mma_f16(d[mi][ni], ra[mi].x, rb[mi].x, ra[mi].y, rb[mi].y, sb.x, sb.y);
                mma_f16(d[mi][ni], ra[mi].z, rb[mi].z, ra[mi].w, rb[mi].w, sb.z, sb.w);
            }
        }
    }

    // ---- Epilogue: + proj_b, fp32 out (valid rows only)
    #pragma unroll
    for (int mi = 0; mi < 2; mi++) {
        int i0 = wm * 32 + mi * 16 + g;
        int i1 = i0 + 8;
        #pragma unroll
        for (int ni = 0; ni < 4; ni++) {
            int n0 = wn * 32 + ni * 8 + 2 * q;
            float2 pb = *(const float2*)(proj_b + n0);
            if (i0 < NTOK) {
                float2 v = make_float2(d[mi][ni][0] + pb.x, d[mi][ni][1] + pb.y);
                *(float2*)(out + ((size_t)b * NTOK + i0) * DIM + n0) = v;
            }
            if (i1 < NTOK) {
                float2 v = make_float2(d[mi][ni][2] + pb.x, d[mi][ni][3] + pb.y);
                *(float2*)(out + ((size_t)b * NTOK + i1) * DIM + n0) = v;
            }
        }
    }
}

// ---------------------------------------------------------------------------
extern "C" void kernel_launch(void* const* d_in, const int* in_sizes, int n_in,
                              void* d_out, int out_size)
{
    const float* x      = (const float*)d_in[0];
    const float* mask   = (const float*)d_in[1];
    const float* qkv_w  = (const float*)d_in[2];
    const float* qkv_b  = (const float*)d_in[3];
    const float* rpb    = (const float*)d_in[4];
    const float* proj_w = (const float*)d_in[5];
    const float* proj_b = (const float*)d_in[6];
    float* out = (float*)d_out;

    __half *xh, *qkvh, *w1h, *w2h, *biash;
    cudaGetSymbolAddress((void**)&xh, g_xh);
    cudaGetSymbolAddress((void**)&qkvh, g_qkvh);
    cudaGetSymbolAddress((void**)&w1h, g_w1h);
    cudaGetSymbolAddress((void**)&w2h, g_w2h);
    cudaGetSymbolAddress((void**)&biash, g_biash);

    cudaFuncSetAttribute(gemm_h,
                         cudaFuncAttributeMaxDynamicSharedMemorySize, GEMM_SMEM_H);
    cudaFuncSetAttribute(attn_proj_fused,
                         cudaFuncAttributeMaxDynamicSharedMemorySize, FUSE_SMEM);

    // 0) Pre-passes
    int n4 = MTOK * DIM / 4;
    f2h_kernel<<<(n4 + 255) / 256, 256>>>(x, xh, n4);
    prep_kernel<<<(PREP_TOTAL + 255) / 256, 256>>>(qkv_w, proj_w, rpb,
                                                   w1h, w2h, biash);

    // 1) QKV GEMM (fp16)
    gemm_h<<<dim3(QKV_N / 128, MTOK / 128), 256, GEMM_SMEM_H>>>(
        xh, w1h, qkv_b, qkvh, QKV_N);

    // 2) Fused attention + projection (fp32 out)
    attn_proj_fused<<<BATCH, 512, FUSE_SMEM>>>(
        qkvh, mask, biash, w2h, proj_b, out);
}